// round 2
// baseline (speedup 1.0000x reference)
#include <cuda_runtime.h>

#define Dh 128
#define DINx 64
#define NLV 15
#define EMAX 20480
#define NPMAX 8192
#define TILE_E 64
#define TILE_G 32

__device__ float g_msg[NPMAX * Dh];
__device__ int g_eperm[NLV * EMAX];
__device__ int g_nperm[NLV * NPMAX];
__device__ int g_ecnt[NLV][5], g_ncnt[NLV][5];
__device__ int g_ecur[NLV][5], g_ncur[NLV][5];
__device__ int g_eoff[NLV][5], g_noff[NLV][5];
__device__ int g_etile[NLV][6], g_ntile[NLV][6];

// code -> ti in CODES=(3,2,5,1,4): c_TI[code]
__constant__ int c_TI[6] = {0, 3, 1, 0, 4, 2};

__device__ __forceinline__ float sigmf(float x) { return 1.f / (1.f + __expf(-x)); }
__device__ __forceinline__ float tanhff(float x) { float e = __expf(2.f * x); return 1.f - 2.f / (e + 1.f); }

__global__ __launch_bounds__(256) void k_zero() {
    int i = blockIdx.x * blockDim.x + threadIdx.x;
    if (i < NPMAX * Dh) g_msg[i] = 0.f;
    if (i < NLV * 5) {
        int l = i / 5, t = i % 5;
        g_ecnt[l][t] = 0; g_ncnt[l][t] = 0; g_ecur[l][t] = 0; g_ncur[l][t] = 0;
    }
}

__global__ __launch_bounds__(256) void k_count(const int* __restrict__ eg, const int* __restrict__ ng, int Epad, int NP) {
    int i = blockIdx.x * blockDim.x + threadIdx.x;
    int ne = NLV * Epad;
    if (i < ne) {
        int g = eg[i];
        if (g > 0) atomicAdd(&g_ecnt[i / Epad][g - 1], 1);
    } else {
        int j = i - ne;
        if (j < NLV * NP) {
            int g = ng[j];
            if (g > 0) atomicAdd(&g_ncnt[j / NP][g - 1], 1);
        }
    }
}

__global__ void k_scan() {
    int l = threadIdx.x;
    if (l >= NLV) return;
    int off = 0, to = 0;
    for (int t = 0; t < 5; t++) {
        g_eoff[l][t] = off; g_etile[l][t] = to;
        off += g_ecnt[l][t]; to += (g_ecnt[l][t] + TILE_E - 1) / TILE_E;
    }
    g_etile[l][5] = to;
    off = 0; to = 0;
    for (int t = 0; t < 5; t++) {
        g_noff[l][t] = off; g_ntile[l][t] = to;
        off += g_ncnt[l][t]; to += (g_ncnt[l][t] + TILE_G - 1) / TILE_G;
    }
    g_ntile[l][5] = to;
}

__global__ __launch_bounds__(256) void k_scatter(const int* __restrict__ eg, const int* __restrict__ ng, int Epad, int NP) {
    int i = blockIdx.x * blockDim.x + threadIdx.x;
    int ne = NLV * Epad;
    if (i < ne) {
        int g = eg[i];
        if (g > 0) {
            int l = i / Epad;
            int p = g_eoff[l][g - 1] + atomicAdd(&g_ecur[l][g - 1], 1);
            g_eperm[l * EMAX + p] = i % Epad;
        }
    } else {
        int j = i - ne;
        if (j < NLV * NP) {
            int g = ng[j];
            if (g > 0) {
                int l = j / NP;
                int p = g_noff[l][g - 1] + atomicAdd(&g_ncur[l][g - 1], 1);
                g_nperm[l * NPMAX + p] = j % NP;
            }
        }
    }
}

__global__ __launch_bounds__(256)
void k_inputs(const float* __restrict__ x, const float* __restrict__ Ws, const float* __restrict__ Wt,
              float* __restrict__ sb, float* __restrict__ tb, float* __restrict__ hb, int N) {
    extern __shared__ float sm[];
    float* smx = sm;                // 64*64
    float* sws = sm + 4096;         // 64*128
    float* swt = sws + 8192;        // 64*128
    int tid = threadIdx.x, row0 = blockIdx.x * 64;
    for (int i = tid; i < 8192; i += 256) { sws[i] = Ws[i]; swt[i] = Wt[i]; }
    for (int i = tid; i < 4096; i += 256) {
        int r = i >> 6, gr = row0 + r;
        smx[i] = (gr < N) ? x[gr * DINx + (i & 63)] : 0.f;
    }
    __syncthreads();
    int tx = tid & 31, ty = tid >> 5;
    float as[8][4] = {}, at[8][4] = {};
    #pragma unroll 4
    for (int k = 0; k < 64; k++) {
        float4 bs = *(float4*)&sws[k * 128 + tx * 4];
        float4 bt = *(float4*)&swt[k * 128 + tx * 4];
        #pragma unroll
        for (int r = 0; r < 8; r++) {
            float a = smx[(ty * 8 + r) * 64 + k];
            as[r][0] += a * bs.x; as[r][1] += a * bs.y; as[r][2] += a * bs.z; as[r][3] += a * bs.w;
            at[r][0] += a * bt.x; at[r][1] += a * bt.y; at[r][2] += a * bt.z; at[r][3] += a * bt.w;
        }
    }
    #pragma unroll
    for (int r = 0; r < 8; r++) {
        int gr = row0 + ty * 8 + r;
        if (gr < N) {
            *(float4*)&sb[gr * Dh + tx * 4] = make_float4(as[r][0], as[r][1], as[r][2], as[r][3]);
            *(float4*)&tb[gr * Dh + tx * 4] = make_float4(at[r][0], at[r][1], at[r][2], at[r][3]);
            *(float4*)&hb[gr * Dh + tx * 4] = make_float4(0.f, 0.f, 0.f, 0.f);
        }
    }
}

__global__ __launch_bounds__(256)
void k_mlp(const float* __restrict__ W1, const float* __restrict__ B1,
           const float* __restrict__ W2, const float* __restrict__ B2,
           const float* __restrict__ W3, const float* __restrict__ B3,
           const int* __restrict__ src_lv, const int* __restrict__ dpos_lv,
           const float* __restrict__ sb, const float* __restrict__ hb, int level, int Epad) {
    extern __shared__ float sm[];
    float* smF = sm;                // 64*256 (feats; then h1 at [0,8192), h2 at [8192,16384))
    float* smW = sm + 16384;        // 64*128
    __shared__ int s_src[TILE_E], s_dp[TILE_E], s_meta[3];
    int tid = threadIdx.x;
    if (tid == 0) {
        int b = blockIdx.x, tot = g_etile[level][5], tc = -1, base = 0, ne = 0;
        if (b < tot) {
            int t2 = 0;
            while (b >= g_etile[level][t2 + 1]) t2++;
            base = g_eoff[level][t2] + (b - g_etile[level][t2]) * TILE_E;
            ne = min(TILE_E, g_eoff[level][t2] + g_ecnt[level][t2] - base);
            tc = t2;
        }
        s_meta[0] = tc; s_meta[1] = base; s_meta[2] = ne;
    }
    __syncthreads();
    int tc = s_meta[0];
    if (tc < 0) return;
    int base = s_meta[1], ne = s_meta[2], ti = c_TI[tc + 1];
    for (int i = tid; i < ne; i += 256) {
        int e = g_eperm[level * EMAX + base + i];
        s_src[i] = src_lv[level * Epad + e];
        s_dp[i] = dpos_lv[level * Epad + e];
    }
    __syncthreads();
    for (int i = tid; i < ne * 256; i += 256) {
        int r = i >> 8, c = i & 255, s = s_src[r];
        smF[i] = (c < 128) ? sb[s * Dh + c] : hb[s * Dh + (c - 128)];
    }
    int tx = tid & 31, ty = tid >> 5;
    float acc[8][4];
    const float* Wp;

    // layer 1
    #pragma unroll
    for (int r = 0; r < 8; r++) { acc[r][0] = acc[r][1] = acc[r][2] = acc[r][3] = 0.f; }
    Wp = W1 + ti * 2 * Dh * Dh;
    for (int k0 = 0; k0 < 256; k0 += 64) {
        __syncthreads();
        for (int i = tid; i < 8192; i += 256) smW[i] = Wp[k0 * 128 + i];
        __syncthreads();
        #pragma unroll 4
        for (int k = 0; k < 64; k++) {
            float4 bv = *(float4*)&smW[k * 128 + tx * 4];
            #pragma unroll
            for (int r = 0; r < 8; r++) {
                float a = smF[(ty * 8 + r) * 256 + k0 + k];
                acc[r][0] += a * bv.x; acc[r][1] += a * bv.y; acc[r][2] += a * bv.z; acc[r][3] += a * bv.w;
            }
        }
    }
    __syncthreads();
    float* sH1 = smF;
    float* sH2 = smF + 8192;
    {
        float4 bb = *(const float4*)&B1[ti * Dh + tx * 4];
        #pragma unroll
        for (int r = 0; r < 8; r++)
            *(float4*)&sH1[(ty * 8 + r) * 128 + tx * 4] = make_float4(
                fmaxf(acc[r][0] + bb.x, 0.f), fmaxf(acc[r][1] + bb.y, 0.f),
                fmaxf(acc[r][2] + bb.z, 0.f), fmaxf(acc[r][3] + bb.w, 0.f));
    }
    __syncthreads();

    // layer 2
    #pragma unroll
    for (int r = 0; r < 8; r++) { acc[r][0] = acc[r][1] = acc[r][2] = acc[r][3] = 0.f; }
    Wp = W2 + ti * Dh * Dh;
    for (int k0 = 0; k0 < 128; k0 += 64) {
        __syncthreads();
        for (int i = tid; i < 8192; i += 256) smW[i] = Wp[k0 * 128 + i];
        __syncthreads();
        #pragma unroll 4
        for (int k = 0; k < 64; k++) {
            float4 bv = *(float4*)&smW[k * 128 + tx * 4];
            #pragma unroll
            for (int r = 0; r < 8; r++) {
                float a = sH1[(ty * 8 + r) * 128 + k0 + k];
                acc[r][0] += a * bv.x; acc[r][1] += a * bv.y; acc[r][2] += a * bv.z; acc[r][3] += a * bv.w;
            }
        }
    }
    __syncthreads();
    {
        float4 bb = *(const float4*)&B2[ti * Dh + tx * 4];
        #pragma unroll
        for (int r = 0; r < 8; r++)
            *(float4*)&sH2[(ty * 8 + r) * 128 + tx * 4] = make_float4(
                fmaxf(acc[r][0] + bb.x, 0.f), fmaxf(acc[r][1] + bb.y, 0.f),
                fmaxf(acc[r][2] + bb.z, 0.f), fmaxf(acc[r][3] + bb.w, 0.f));
    }
    __syncthreads();

    // layer 3 + scatter
    #pragma unroll
    for (int r = 0; r < 8; r++) { acc[r][0] = acc[r][1] = acc[r][2] = acc[r][3] = 0.f; }
    Wp = W3 + ti * Dh * Dh;
    for (int k0 = 0; k0 < 128; k0 += 64) {
        __syncthreads();
        for (int i = tid; i < 8192; i += 256) smW[i] = Wp[k0 * 128 + i];
        __syncthreads();
        #pragma unroll 4
        for (int k = 0; k < 64; k++) {
            float4 bv = *(float4*)&smW[k * 128 + tx * 4];
            #pragma unroll
            for (int r = 0; r < 8; r++) {
                float a = sH2[(ty * 8 + r) * 128 + k0 + k];
                acc[r][0] += a * bv.x; acc[r][1] += a * bv.y; acc[r][2] += a * bv.z; acc[r][3] += a * bv.w;
            }
        }
    }
    {
        float4 bb = *(const float4*)&B3[ti * Dh + tx * 4];
        #pragma unroll
        for (int r = 0; r < 8; r++) {
            int row = ty * 8 + r;
            if (row < ne) {
                float* mp = &g_msg[s_dp[row] * Dh + tx * 4];
                atomicAdd(mp + 0, acc[r][0] + bb.x);
                atomicAdd(mp + 1, acc[r][1] + bb.y);
                atomicAdd(mp + 2, acc[r][2] + bb.z);
                atomicAdd(mp + 3, acc[r][3] + bb.w);
            }
        }
    }
}

__global__ __launch_bounds__(256)
void k_gru(const float* __restrict__ Wih, const float* __restrict__ Whh,
           const float* __restrict__ bih, const float* __restrict__ bhh,
           const int* __restrict__ node_lv, float* __restrict__ sb, float* __restrict__ hb,
           int level, int NP) {
    extern __shared__ float sm[];
    float* smX = sm;            // 32*128
    float* smH = sm + 4096;     // 32*128
    float* smW = sm + 8192;     // 32*384
    __shared__ int s_pos[TILE_G], s_node[TILE_G], s_meta[3];
    int tid = threadIdx.x;
    if (tid == 0) {
        int b = blockIdx.x, tot = g_ntile[level][5], tc = -1, base = 0, nn = 0;
        if (b < tot) {
            int t2 = 0;
            while (b >= g_ntile[level][t2 + 1]) t2++;
            base = g_noff[level][t2] + (b - g_ntile[level][t2]) * TILE_G;
            nn = min(TILE_G, g_noff[level][t2] + g_ncnt[level][t2] - base);
            tc = t2;
        }
        s_meta[0] = tc; s_meta[1] = base; s_meta[2] = nn;
    }
    __syncthreads();
    int tc = s_meta[0];
    if (tc < 0) return;
    int base = s_meta[1], nn = s_meta[2], ti = c_TI[tc + 1];
    for (int i = tid; i < nn; i += 256) {
        int p = g_nperm[level * NPMAX + base + i];
        s_pos[i] = p;
        s_node[i] = node_lv[level * NP + p];
    }
    __syncthreads();
    for (int i = tid; i < nn * Dh; i += 256) {
        int r = i >> 7, c = i & 127, p = s_pos[r];
        smX[i] = g_msg[p * Dh + c];
        g_msg[p * Dh + c] = 0.f;
        smH[i] = hb[s_node[r] * Dh + c];
    }
    __syncthreads();
    int tx = tid & 31, ty = tid >> 5;
    float gi[4][12];
    #pragma unroll
    for (int r = 0; r < 4; r++)
        #pragma unroll
        for (int c = 0; c < 12; c++) gi[r][c] = 0.f;

    const float* Wp = Wih + ti * Dh * 3 * Dh;
    for (int k0 = 0; k0 < 128; k0 += 32) {
        __syncthreads();
        for (int i = tid; i < 12288; i += 256) smW[i] = Wp[k0 * 384 + i];
        __syncthreads();
        #pragma unroll 4
        for (int k = 0; k < 32; k++) {
            float4 b0 = *(float4*)&smW[k * 384 + tx * 4];
            float4 b1 = *(float4*)&smW[k * 384 + 128 + tx * 4];
            float4 b2 = *(float4*)&smW[k * 384 + 256 + tx * 4];
            #pragma unroll
            for (int r = 0; r < 4; r++) {
                float a = smX[(ty * 4 + r) * 128 + k0 + k];
                gi[r][0] += a * b0.x; gi[r][1] += a * b0.y; gi[r][2] += a * b0.z; gi[r][3] += a * b0.w;
                gi[r][4] += a * b1.x; gi[r][5] += a * b1.y; gi[r][6] += a * b1.z; gi[r][7] += a * b1.w;
                gi[r][8] += a * b2.x; gi[r][9] += a * b2.y; gi[r][10] += a * b2.z; gi[r][11] += a * b2.w;
            }
        }
    }
    {
        const float* bp = bih + ti * 384;
        float4 c0 = *(const float4*)&bp[tx * 4];
        float4 c1 = *(const float4*)&bp[128 + tx * 4];
        float4 c2 = *(const float4*)&bp[256 + tx * 4];
        #pragma unroll
        for (int r = 0; r < 4; r++) {
            gi[r][0] += c0.x; gi[r][1] += c0.y; gi[r][2] += c0.z; gi[r][3] += c0.w;
            gi[r][4] += c1.x; gi[r][5] += c1.y; gi[r][6] += c1.z; gi[r][7] += c1.w;
            gi[r][8] += c2.x; gi[r][9] += c2.y; gi[r][10] += c2.z; gi[r][11] += c2.w;
        }
    }
    const float* Whp = Whh + ti * Dh * 3 * Dh;
    const float* bhp = bhh + ti * 384;
    float4 d0 = *(const float4*)&bhp[tx * 4];
    float4 d1 = *(const float4*)&bhp[128 + tx * 4];
    float4 d2 = *(const float4*)&bhp[256 + tx * 4];

    int npass = (tc + 1 == 3) ? 2 : 1;
    for (int pass = 0; pass < npass; pass++) {
        if (pass == 1) {
            __syncthreads();
            for (int i = tid; i < nn * Dh; i += 256)
                smH[i] = sb[s_node[i >> 7] * Dh + (i & 127)];
            __syncthreads();
        }
        float gh[4][12];
        #pragma unroll
        for (int r = 0; r < 4; r++)
            #pragma unroll
            for (int c = 0; c < 12; c++) gh[r][c] = 0.f;
        for (int k0 = 0; k0 < 128; k0 += 32) {
            __syncthreads();
            for (int i = tid; i < 12288; i += 256) smW[i] = Whp[k0 * 384 + i];
            __syncthreads();
            #pragma unroll 4
            for (int k = 0; k < 32; k++) {
                float4 b0 = *(float4*)&smW[k * 384 + tx * 4];
                float4 b1 = *(float4*)&smW[k * 384 + 128 + tx * 4];
                float4 b2 = *(float4*)&smW[k * 384 + 256 + tx * 4];
                #pragma unroll
                for (int r = 0; r < 4; r++) {
                    float a = smH[(ty * 4 + r) * 128 + k0 + k];
                    gh[r][0] += a * b0.x; gh[r][1] += a * b0.y; gh[r][2] += a * b0.z; gh[r][3] += a * b0.w;
                    gh[r][4] += a * b1.x; gh[r][5] += a * b1.y; gh[r][6] += a * b1.z; gh[r][7] += a * b1.w;
                    gh[r][8] += a * b2.x; gh[r][9] += a * b2.y; gh[r][10] += a * b2.z; gh[r][11] += a * b2.w;
                }
            }
        }
        float* target = pass ? sb : hb;
        #pragma unroll
        for (int r = 0; r < 4; r++) {
            int row = ty * 4 + r;
            if (row < nn) {
                float4 o;
                float* op = (float*)&o;
                #pragma unroll
                for (int c = 0; c < 4; c++) {
                    float rv = sigmf(gi[r][c] + gh[r][c] + d0.x * 0.f + ((float*)&d0)[c]);
                    float zv = sigmf(gi[r][4 + c] + gh[r][4 + c] + ((float*)&d1)[c]);
                    float nv = tanhff(gi[r][8 + c] + rv * (gh[r][8 + c] + ((float*)&d2)[c]));
                    float h = smH[row * Dh + tx * 4 + c];
                    op[c] = (1.f - zv) * nv + zv * h;
                }
                *(float4*)&target[s_node[row] * Dh + tx * 4] = o;
            }
        }
    }
}

extern "C" void kernel_launch(void* const* d_in, const int* in_sizes, int n_in,
                              void* d_out, int out_size) {
    const float* x = (const float*)d_in[0];
    const float* Ws = (const float*)d_in[1];
    const float* Wt = (const float*)d_in[2];
    const float* aW1 = (const float*)d_in[3];
    const float* ab1 = (const float*)d_in[4];
    const float* aW2 = (const float*)d_in[5];
    const float* ab2 = (const float*)d_in[6];
    const float* aW3 = (const float*)d_in[7];
    const float* ab3 = (const float*)d_in[8];
    const float* gWih = (const float*)d_in[9];
    const float* gWhh = (const float*)d_in[10];
    const float* gbih = (const float*)d_in[11];
    const float* gbhh = (const float*)d_in[12];
    const int* src_lv = (const int*)d_in[13];
    const int* dpos_lv = (const int*)d_in[14];
    const int* egate_lv = (const int*)d_in[15];
    const int* node_lv = (const int*)d_in[16];
    const int* ngate_lv = (const int*)d_in[17];

    int N = in_sizes[0] / DINx;
    int Epad = in_sizes[13] / NLV;
    int NP = in_sizes[16] / NLV;

    float* sb = (float*)d_out;
    float* tb = sb + (size_t)N * Dh;
    float* hb = tb + (size_t)N * Dh;

    const int SM_IN = (4096 + 2 * 8192) * 4;
    const int SM_MLP = (16384 + 8192) * 4;
    const int SM_GRU = (8192 + 12288) * 4;
    static bool attr_done = false;
    if (!attr_done) {
        cudaFuncSetAttribute(k_inputs, cudaFuncAttributeMaxDynamicSharedMemorySize, SM_IN);
        cudaFuncSetAttribute(k_mlp, cudaFuncAttributeMaxDynamicSharedMemorySize, SM_MLP);
        cudaFuncSetAttribute(k_gru, cudaFuncAttributeMaxDynamicSharedMemorySize, SM_GRU);
        attr_done = true;
    }

    k_zero<<<(NPMAX * Dh + 255) / 256, 256>>>();
    int tot_cs = NLV * Epad + NLV * NP;
    k_count<<<(tot_cs + 255) / 256, 256>>>(egate_lv, ngate_lv, Epad, NP);
    k_scan<<<1, 32>>>();
    k_scatter<<<(tot_cs + 255) / 256, 256>>>(egate_lv, ngate_lv, Epad, NP);
    k_inputs<<<(N + 63) / 64, 256, SM_IN>>>(x, Ws, Wt, sb, tb, hb, N);

    int mlp_grid = (Epad + TILE_E - 1) / TILE_E + 5;
    int gru_grid = (NP + TILE_G - 1) / TILE_G + 5;
    for (int l = 0; l < NLV; l++) {
        k_mlp<<<mlp_grid, 256, SM_MLP>>>(aW1, ab1, aW2, ab2, aW3, ab3,
                                         src_lv, dpos_lv, sb, hb, l, Epad);
        k_gru<<<gru_grid, 256, SM_GRU>>>(gWih, gWhh, gbih, gbhh,
                                         node_lv, sb, hb, l, NP);
    }
}

// round 5
// speedup vs baseline: 1.2736x; 1.2736x over previous
#include <cuda_runtime.h>
#include <cuda_bf16.h>
#include <cstdint>

#define Dh 128
#define DINx 64
#define NLV 15
#define EMAX 20480
#define NPMAX 8192
#define TILE_E 64
#define TILE_G 32

__device__ float g_msg[NPMAX * Dh];
__device__ int g_eperm[NLV * EMAX];
__device__ int g_nperm[NLV * NPMAX];
__device__ int g_ecnt[NLV][5], g_ncnt[NLV][5];
__device__ int g_ecur[NLV][5], g_ncur[NLV][5];
__device__ int g_eoff[NLV][5], g_noff[NLV][5];
__device__ int g_etile[NLV][6], g_ntile[NLV][6];

// pre-split weights (hi/lo bf16)
__device__ __nv_bfloat16 g_W1h[5 * 256 * 128], g_W1l[5 * 256 * 128];
__device__ __nv_bfloat16 g_W2h[5 * 128 * 128], g_W2l[5 * 128 * 128];
__device__ __nv_bfloat16 g_W3h[5 * 128 * 128], g_W3l[5 * 128 * 128];
__device__ __nv_bfloat16 g_Wih_h[5 * 128 * 384], g_Wih_l[5 * 128 * 384];
__device__ __nv_bfloat16 g_Whh_h[5 * 128 * 384], g_Whh_l[5 * 128 * 384];

// code -> ti in CODES=(3,2,5,1,4)
__constant__ int c_TI[6] = {0, 3, 1, 0, 4, 2};

__device__ __forceinline__ float sigmf(float x) { return 1.f / (1.f + __expf(-x)); }
__device__ __forceinline__ float tanhff(float x) { float e = __expf(2.f * x); return 1.f - 2.f / (e + 1.f); }

__device__ __forceinline__ void splitbf(float v, __nv_bfloat16* h, __nv_bfloat16* l) {
    __nv_bfloat16 hh = __float2bfloat16_rn(v);
    *h = hh;
    *l = __float2bfloat16_rn(v - __bfloat162float(hh));
}

__device__ __forceinline__ void ldsm4(uint32_t r[4], const void* p) {
    unsigned int a = (unsigned int)__cvta_generic_to_shared(p);
    asm volatile("ldmatrix.sync.aligned.m8n8.x4.shared.b16 {%0,%1,%2,%3},[%4];"
                 : "=r"(r[0]), "=r"(r[1]), "=r"(r[2]), "=r"(r[3]) : "r"(a));
}
__device__ __forceinline__ void ldsm4t(uint32_t r[4], const void* p) {
    unsigned int a = (unsigned int)__cvta_generic_to_shared(p);
    asm volatile("ldmatrix.sync.aligned.m8n8.x4.trans.shared.b16 {%0,%1,%2,%3},[%4];"
                 : "=r"(r[0]), "=r"(r[1]), "=r"(r[2]), "=r"(r[3]) : "r"(a));
}
__device__ __forceinline__ void mma_bf(float c[4], const uint32_t a[4], uint32_t b0, uint32_t b1) {
    asm volatile(
        "mma.sync.aligned.m16n8k16.row.col.f32.bf16.bf16.f32 "
        "{%0,%1,%2,%3},{%4,%5,%6,%7},{%8,%9},{%0,%1,%2,%3};"
        : "+f"(c[0]), "+f"(c[1]), "+f"(c[2]), "+f"(c[3])
        : "r"(a[0]), "r"(a[1]), "r"(a[2]), "r"(a[3]), "r"(b0), "r"(b1));
}

// ---------------- setup ----------------
__global__ __launch_bounds__(256) void k_zero() {
    int i = blockIdx.x * blockDim.x + threadIdx.x;
    if (i < NPMAX * Dh) g_msg[i] = 0.f;
    if (i < NLV * 5) {
        int l = i / 5, t = i % 5;
        g_ecnt[l][t] = 0; g_ncnt[l][t] = 0; g_ecur[l][t] = 0; g_ncur[l][t] = 0;
    }
}

__global__ __launch_bounds__(256) void k_prep(const float* __restrict__ aW1, const float* __restrict__ aW2,
                                              const float* __restrict__ aW3, const float* __restrict__ gWih,
                                              const float* __restrict__ gWhh) {
    int i = blockIdx.x * 256 + threadIdx.x;
    if (i < 163840) splitbf(aW1[i], &g_W1h[i], &g_W1l[i]);
    else if (i < 245760) { int j = i - 163840; splitbf(aW2[j], &g_W2h[j], &g_W2l[j]); }
    else if (i < 327680) { int j = i - 245760; splitbf(aW3[j], &g_W3h[j], &g_W3l[j]); }
    else if (i < 573440) { int j = i - 327680; splitbf(gWih[j], &g_Wih_h[j], &g_Wih_l[j]); }
    else if (i < 819200) { int j = i - 573440; splitbf(gWhh[j], &g_Whh_h[j], &g_Whh_l[j]); }
}

__global__ __launch_bounds__(256) void k_count(const int* __restrict__ eg, const int* __restrict__ ng, int Epad, int NP) {
    __shared__ int hist[150];
    int tid = threadIdx.x;
    if (tid < 150) hist[tid] = 0;
    __syncthreads();
    int i = blockIdx.x * 256 + tid;
    int ne = NLV * Epad;
    if (i < ne) {
        int g = eg[i];
        if (g > 0) atomicAdd(&hist[(i / Epad) * 5 + g - 1], 1);
    } else {
        int j = i - ne;
        if (j < NLV * NP) {
            int g = ng[j];
            if (g > 0) atomicAdd(&hist[75 + (j / NP) * 5 + g - 1], 1);
        }
    }
    __syncthreads();
    if (tid < 75 && hist[tid]) atomicAdd(&((int*)g_ecnt)[tid], hist[tid]);
    if (tid >= 75 && tid < 150 && hist[tid]) atomicAdd(&((int*)g_ncnt)[tid - 75], hist[tid]);
}

__global__ void k_scan() {
    int l = threadIdx.x;
    if (l >= NLV) return;
    int off = 0, to = 0;
    for (int t = 0; t < 5; t++) {
        g_eoff[l][t] = off; g_etile[l][t] = to;
        off += g_ecnt[l][t]; to += (g_ecnt[l][t] + TILE_E - 1) / TILE_E;
    }
    g_etile[l][5] = to;
    off = 0; to = 0;
    for (int t = 0; t < 5; t++) {
        g_noff[l][t] = off; g_ntile[l][t] = to;
        off += g_ncnt[l][t]; to += (g_ncnt[l][t] + TILE_G - 1) / TILE_G;
    }
    g_ntile[l][5] = to;
}

__global__ __launch_bounds__(256) void k_scatter(const int* __restrict__ eg, const int* __restrict__ ng, int Epad, int NP) {
    __shared__ int hist[150], basev[150], lcur[150];
    int tid = threadIdx.x;
    if (tid < 150) { hist[tid] = 0; lcur[tid] = 0; }
    __syncthreads();
    int i = blockIdx.x * 256 + tid;
    int ne = NLV * Epad;
    int bin = -1;
    if (i < ne) {
        int g = eg[i];
        if (g > 0) bin = (i / Epad) * 5 + g - 1;
    } else {
        int j = i - ne;
        if (j < NLV * NP) {
            int g = ng[j];
            if (g > 0) bin = 75 + (j / NP) * 5 + g - 1;
        }
    }
    if (bin >= 0) atomicAdd(&hist[bin], 1);
    __syncthreads();
    if (tid < 75 && hist[tid]) basev[tid] = atomicAdd(&((int*)g_ecur)[tid], hist[tid]);
    if (tid >= 75 && tid < 150 && hist[tid]) basev[tid] = atomicAdd(&((int*)g_ncur)[tid - 75], hist[tid]);
    __syncthreads();
    if (bin >= 0) {
        int p = basev[bin] + atomicAdd(&lcur[bin], 1);
        if (bin < 75) {
            int l = bin / 5;
            g_eperm[l * EMAX + ((int*)g_eoff)[bin] + p] = i % Epad;
        } else {
            int l = (bin - 75) / 5;
            g_nperm[l * NPMAX + ((int*)g_noff)[bin - 75] + p] = (i - ne) % NP;
        }
    }
}

// ---------------- input projections (fp32 SIMT) ----------------
__global__ __launch_bounds__(256)
void k_inputs(const float* __restrict__ x, const float* __restrict__ Ws, const float* __restrict__ Wt,
              float* __restrict__ sb, float* __restrict__ tb, float* __restrict__ hb, int N) {
    extern __shared__ float sm[];
    float* smx = sm;
    float* sws = sm + 4096;
    float* swt = sws + 8192;
    int tid = threadIdx.x, row0 = blockIdx.x * 64;
    for (int i = tid; i < 8192; i += 256) { sws[i] = Ws[i]; swt[i] = Wt[i]; }
    for (int i = tid; i < 4096; i += 256) {
        int r = i >> 6, gr = row0 + r;
        smx[i] = (gr < N) ? x[gr * DINx + (i & 63)] : 0.f;
    }
    __syncthreads();
    int tx = tid & 31, ty = tid >> 5;
    float as[8][4] = {}, at[8][4] = {};
    #pragma unroll 4
    for (int k = 0; k < 64; k++) {
        float4 bs = *(float4*)&sws[k * 128 + tx * 4];
        float4 bt = *(float4*)&swt[k * 128 + tx * 4];
        #pragma unroll
        for (int r = 0; r < 8; r++) {
            float a = smx[(ty * 8 + r) * 64 + k];
            as[r][0] += a * bs.x; as[r][1] += a * bs.y; as[r][2] += a * bs.z; as[r][3] += a * bs.w;
            at[r][0] += a * bt.x; at[r][1] += a * bt.y; at[r][2] += a * bt.z; at[r][3] += a * bt.w;
        }
    }
    #pragma unroll
    for (int r = 0; r < 8; r++) {
        int gr = row0 + ty * 8 + r;
        if (gr < N) {
            *(float4*)&sb[gr * Dh + tx * 4] = make_float4(as[r][0], as[r][1], as[r][2], as[r][3]);
            *(float4*)&tb[gr * Dh + tx * 4] = make_float4(at[r][0], at[r][1], at[r][2], at[r][3]);
            *(float4*)&hb[gr * Dh + tx * 4] = make_float4(0.f, 0.f, 0.f, 0.f);
        }
    }
}

// ---------------- MLP: 64-edge tile, mma bf16-split ----------------
#define MLP_SMEM 137216
__global__ __launch_bounds__(256)
void k_mlp(const float* __restrict__ B1, const float* __restrict__ B2, const float* __restrict__ B3,
           const int* __restrict__ src_lv, const int* __restrict__ dpos_lv,
           const float* __restrict__ sb, const float* __restrict__ hb, int level, int Epad) {
    extern __shared__ char smc[];
    __nv_bfloat16* Ah  = (__nv_bfloat16*)smc;                 // stride 264 (layer1) / 136 (as H2)
    __nv_bfloat16* Al  = (__nv_bfloat16*)(smc + 33792);
    __nv_bfloat16* H1h = (__nv_bfloat16*)(smc + 67584);       // stride 136
    __nv_bfloat16* H1l = (__nv_bfloat16*)(smc + 84992);
    __nv_bfloat16* Wh  = (__nv_bfloat16*)(smc + 102400);      // stride 136, 64 rows
    __nv_bfloat16* Wl  = (__nv_bfloat16*)(smc + 119808);
    __shared__ int s_src[TILE_E], s_dp[TILE_E], s_meta[3];

    int tid = threadIdx.x;
    if (tid == 0) {
        int b = blockIdx.x, tot = g_etile[level][5], tc = -1, base = 0, ne = 0;
        if (b < tot) {
            int t2 = 0;
            while (b >= g_etile[level][t2 + 1]) t2++;
            base = g_eoff[level][t2] + (b - g_etile[level][t2]) * TILE_E;
            ne = min(TILE_E, g_eoff[level][t2] + g_ecnt[level][t2] - base);
            tc = t2;
        }
        s_meta[0] = tc; s_meta[1] = base; s_meta[2] = ne;
    }
    __syncthreads();
    int tc = s_meta[0];
    if (tc < 0) return;
    int base = s_meta[1], ne = s_meta[2], ti = c_TI[tc + 1];
    for (int i = tid; i < ne; i += 256) {
        int e = g_eperm[level * EMAX + base + i];
        s_src[i] = src_lv[level * Epad + e];
        s_dp[i] = dpos_lv[level * Epad + e];
    }
    __syncthreads();
    for (int i = tid; i < 64 * 256; i += 256) {
        int r = i >> 8, c = i & 255;
        float v = 0.f;
        if (r < ne) {
            int s = s_src[r];
            v = (c < 128) ? sb[s * Dh + c] : hb[s * Dh + (c - 128)];
        }
        splitbf(v, &Ah[r * 264 + c], &Al[r * 264 + c]);
    }

    int lane = tid & 31, warp = tid >> 5, wr = warp >> 1, wc = warp & 1;
    float acc[8][4];

    auto run_gemm = [&](const __nv_bfloat16* sAh, const __nv_bfloat16* sAl, int lda, int K,
                        const __nv_bfloat16* gwh, const __nv_bfloat16* gwl) {
        #pragma unroll
        for (int t = 0; t < 8; t++) { acc[t][0] = acc[t][1] = acc[t][2] = acc[t][3] = 0.f; }
        for (int kc = 0; kc < K; kc += 64) {
            __syncthreads();
            for (int i = tid; i < 4096; i += 256) {
                int r = i >> 6, c2 = (i & 63) << 1;
                *(uint32_t*)&Wh[r * 136 + c2] = *(const uint32_t*)&gwh[(kc + r) * 128 + c2];
                *(uint32_t*)&Wl[r * 136 + c2] = *(const uint32_t*)&gwl[(kc + r) * 128 + c2];
            }
            __syncthreads();
            #pragma unroll
            for (int ks = 0; ks < 4; ks++) {
                int k0 = ks << 4;
                uint32_t ah[4], al[4];
                const __nv_bfloat16* ap = sAh + (wr * 16 + (lane & 15)) * lda + kc + k0 + ((lane >> 4) << 3);
                ldsm4(ah, ap);
                ldsm4(al, sAl + (ap - sAh));
                #pragma unroll
                for (int g = 0; g < 4; g++) {
                    int c0 = wc * 64 + (g << 4);
                    uint32_t bh[4], bl[4];
                    const __nv_bfloat16* bp = Wh + (k0 + (lane & 15)) * 136 + c0 + ((lane >> 4) << 3);
                    ldsm4t(bh, bp);
                    ldsm4t(bl, Wl + (bp - Wh));
                    mma_bf(acc[2 * g], ah, bh[0], bh[1]);
                    mma_bf(acc[2 * g], ah, bl[0], bl[1]);
                    mma_bf(acc[2 * g], al, bh[0], bh[1]);
                    mma_bf(acc[2 * g + 1], ah, bh[2], bh[3]);
                    mma_bf(acc[2 * g + 1], ah, bl[2], bl[3]);
                    mma_bf(acc[2 * g + 1], al, bh[2], bh[3]);
                }
            }
        }
        __syncthreads();
    };

    int r1 = wr * 16 + (lane >> 2), r2 = r1 + 8;

    auto store_relu = [&](__nv_bfloat16* Dhp, __nv_bfloat16* Dlp, const float* bias) {
        #pragma unroll
        for (int t = 0; t < 8; t++) {
            int col = wc * 64 + t * 8 + ((lane & 3) << 1);
            float b0 = bias[col], b1 = bias[col + 1];
            splitbf(fmaxf(acc[t][0] + b0, 0.f), &Dhp[r1 * 136 + col], &Dlp[r1 * 136 + col]);
            splitbf(fmaxf(acc[t][1] + b1, 0.f), &Dhp[r1 * 136 + col + 1], &Dlp[r1 * 136 + col + 1]);
            splitbf(fmaxf(acc[t][2] + b0, 0.f), &Dhp[r2 * 136 + col], &Dlp[r2 * 136 + col]);
            splitbf(fmaxf(acc[t][3] + b1, 0.f), &Dhp[r2 * 136 + col + 1], &Dlp[r2 * 136 + col + 1]);
        }
    };

    run_gemm(Ah, Al, 264, 256, g_W1h + ti * 32768, g_W1l + ti * 32768);
    store_relu(H1h, H1l, B1 + ti * Dh);
    run_gemm(H1h, H1l, 136, 128, g_W2h + ti * 16384, g_W2l + ti * 16384);
    store_relu(Ah, Al, B2 + ti * Dh);
    run_gemm(Ah, Al, 136, 128, g_W3h + ti * 16384, g_W3l + ti * 16384);
    {
        const float* bias = B3 + ti * Dh;
        #pragma unroll
        for (int t = 0; t < 8; t++) {
            int col = wc * 64 + t * 8 + ((lane & 3) << 1);
            float b0 = bias[col], b1 = bias[col + 1];
            if (r1 < ne) {
                float* mp = &g_msg[s_dp[r1] * Dh + col];
                atomicAdd(mp, acc[t][0] + b0);
                atomicAdd(mp + 1, acc[t][1] + b1);
            }
            if (r2 < ne) {
                float* mp = &g_msg[s_dp[r2] * Dh + col];
                atomicAdd(mp, acc[t][2] + b0);
                atomicAdd(mp + 1, acc[t][3] + b1);
            }
        }
    }
}

// ---------------- GRU: 32-node tile, mma bf16-split ----------------
#define GRU_SMEM 185344
__global__ __launch_bounds__(256)
void k_gru(const float* __restrict__ gbih, const float* __restrict__ gbhh,
           const int* __restrict__ node_lv, float* __restrict__ sb, float* __restrict__ hb,
           int level, int NP) {
    extern __shared__ char smc[];
    __nv_bfloat16* Xh = (__nv_bfloat16*)smc;
    __nv_bfloat16* Xl = (__nv_bfloat16*)(smc + 8704);
    __nv_bfloat16* Hh = (__nv_bfloat16*)(smc + 17408);
    __nv_bfloat16* Hl = (__nv_bfloat16*)(smc + 26112);
    __nv_bfloat16* Wh = (__nv_bfloat16*)(smc + 34816);
    __nv_bfloat16* Wl = (__nv_bfloat16*)(smc + 59904);
    float* gi = (float*)(smc + 84992);
    float* gh = (float*)(smc + 135168);
    __shared__ int s_pos[TILE_G], s_node[TILE_G], s_meta[3];

    int tid = threadIdx.x;
    if (tid == 0) {
        int b = blockIdx.x, tot = g_ntile[level][5], tc = -1, base = 0, nn = 0;
        if (b < tot) {
            int t2 = 0;
            while (b >= g_ntile[level][t2 + 1]) t2++;
            base = g_noff[level][t2] + (b - g_ntile[level][t2]) * TILE_G;
            nn = min(TILE_G, g_noff[level][t2] + g_ncnt[level][t2] - base);
            tc = t2;
        }
        s_meta[0] = tc; s_meta[1] = base; s_meta[2] = nn;
    }
    __syncthreads();
    int tc = s_meta[0];
    if (tc < 0) return;
    int base = s_meta[1], nn = s_meta[2], ti = c_TI[tc + 1];
    for (int i = tid; i < nn; i += 256) {
        int p = g_nperm[level * NPMAX + base + i];
        s_pos[i] = p;
        s_node[i] = node_lv[level * NP + p];
    }
    __syncthreads();
    for (int i = tid; i < 32 * 128; i += 256) {
        int r = i >> 7, c = i & 127;
        float xv = 0.f, hv = 0.f;
        if (r < nn) {
            int p = s_pos[r];
            xv = g_msg[p * Dh + c];
            g_msg[p * Dh + c] = 0.f;
            hv = hb[s_node[r] * Dh + c];
        }
        splitbf(xv, &Xh[r * 136 + c], &Xl[r * 136 + c]);
        splitbf(hv, &Hh[r * 136 + c], &Hl[r * 136 + c]);
    }

    int lane = tid & 31, warp = tid >> 5, wr = warp >> 2, wc = warp & 3;
    float acc[12][4];

    auto run_gemm = [&](const __nv_bfloat16* sAh, const __nv_bfloat16* sAl,
                        const __nv_bfloat16* gwh, const __nv_bfloat16* gwl) {
        #pragma unroll
        for (int t = 0; t < 12; t++) { acc[t][0] = acc[t][1] = acc[t][2] = acc[t][3] = 0.f; }
        for (int kc = 0; kc < 128; kc += 32) {
            __syncthreads();
            for (int i = tid; i < 6144; i += 256) {
                int r = i / 192, c2 = (i % 192) * 2;
                *(uint32_t*)&Wh[r * 392 + c2] = *(const uint32_t*)&gwh[(kc + r) * 384 + c2];
                *(uint32_t*)&Wl[r * 392 + c2] = *(const uint32_t*)&gwl[(kc + r) * 384 + c2];
            }
            __syncthreads();
            #pragma unroll
            for (int ks = 0; ks < 2; ks++) {
                int k0 = ks << 4;
                uint32_t ah[4], al[4];
                const __nv_bfloat16* ap = sAh + (wr * 16 + (lane & 15)) * 136 + kc + k0 + ((lane >> 4) << 3);
                ldsm4(ah, ap);
                ldsm4(al, sAl + (ap - sAh));
                #pragma unroll
                for (int g = 0; g < 6; g++) {
                    int c0 = wc * 96 + (g << 4);
                    uint32_t bh[4], bl[4];
                    const __nv_bfloat16* bp = Wh + (k0 + (lane & 15)) * 392 + c0 + ((lane >> 4) << 3);
                    ldsm4t(bh, bp);
                    ldsm4t(bl, Wl + (bp - Wh));
                    mma_bf(acc[2 * g], ah, bh[0], bh[1]);
                    mma_bf(acc[2 * g], ah, bl[0], bl[1]);
                    mma_bf(acc[2 * g], al, bh[0], bh[1]);
                    mma_bf(acc[2 * g + 1], ah, bh[2], bh[3]);
                    mma_bf(acc[2 * g + 1], ah, bl[2], bl[3]);
                    mma_bf(acc[2 * g + 1], al, bh[2], bh[3]);
                }
            }
        }
        __syncthreads();
    };

    int r1 = wr * 16 + (lane >> 2), r2 = r1 + 8;
    auto store_g = [&](float* dst, const float* bias) {
        #pragma unroll
        for (int t = 0; t < 12; t++) {
            int col = wc * 96 + t * 8 + ((lane & 3) << 1);
            float b0 = bias[col], b1 = bias[col + 1];
            dst[r1 * 392 + col] = acc[t][0] + b0;
            dst[r1 * 392 + col + 1] = acc[t][1] + b1;
            dst[r2 * 392 + col] = acc[t][2] + b0;
            dst[r2 * 392 + col + 1] = acc[t][3] + b1;
        }
    };

    run_gemm(Xh, Xl, g_Wih_h + ti * 49152, g_Wih_l + ti * 49152);
    store_g(gi, gbih + ti * 384);

    int npass = (tc == 2) ? 2 : 1;   // AND also refreshes s
    for (int pass = 0; pass < npass; pass++) {
        if (pass == 1) {
            __syncthreads();
            for (int i = tid; i < 32 * 128; i += 256) {
                int r = i >> 7, c = i & 127;
                float hv = (r < nn) ? sb[s_node[r] * Dh + c] : 0.f;
                splitbf(hv, &Hh[r * 136 + c], &Hl[r * 136 + c]);
            }
        }
        run_gemm(Hh, Hl, g_Whh_h + ti * 49152, g_Whh_l + ti * 49152);
        store_g(gh, gbhh + ti * 384);
        __syncthreads();
        float* target = pass ? sb : hb;
        for (int i = tid; i < 32 * 128; i += 256) {
            int r = i >> 7, j = i & 127;
            if (r < nn) {
                float h = __bfloat162float(Hh[r * 136 + j]) + __bfloat162float(Hl[r * 136 + j]);
                float rv = sigmf(gi[r * 392 + j] + gh[r * 392 + j]);
                float zv = sigmf(gi[r * 392 + 128 + j] + gh[r * 392 + 128 + j]);
                float nv = tanhff(gi[r * 392 + 256 + j] + rv * gh[r * 392 + 256 + j]);
                target[s_node[r] * Dh + j] = (1.f - zv) * nv + zv * h;
            }
        }
        __syncthreads();
    }
}

extern "C" void kernel_launch(void* const* d_in, const int* in_sizes, int n_in,
                              void* d_out, int out_size) {
    const float* x = (const float*)d_in[0];
    const float* Ws = (const float*)d_in[1];
    const float* Wt = (const float*)d_in[2];
    const float* aW1 = (const float*)d_in[3];
    const float* ab1 = (const float*)d_in[4];
    const float* aW2 = (const float*)d_in[5];
    const float* ab2 = (const float*)d_in[6];
    const float* aW3 = (const float*)d_in[7];
    const float* ab3 = (const float*)d_in[8];
    const float* gWih = (const float*)d_in[9];
    const float* gWhh = (const float*)d_in[10];
    const float* gbih = (const float*)d_in[11];
    const float* gbhh = (const float*)d_in[12];
    const int* src_lv = (const int*)d_in[13];
    const int* dpos_lv = (const int*)d_in[14];
    const int* egate_lv = (const int*)d_in[15];
    const int* node_lv = (const int*)d_in[16];
    const int* ngate_lv = (const int*)d_in[17];

    int N = in_sizes[0] / DINx;
    int Epad = in_sizes[13] / NLV;
    int NP = in_sizes[16] / NLV;

    float* sb = (float*)d_out;
    float* tb = sb + (size_t)N * Dh;
    float* hb = tb + (size_t)N * Dh;

    const int SM_IN = (4096 + 2 * 8192) * 4;
    cudaFuncSetAttribute(k_inputs, cudaFuncAttributeMaxDynamicSharedMemorySize, SM_IN);
    cudaFuncSetAttribute(k_mlp, cudaFuncAttributeMaxDynamicSharedMemorySize, MLP_SMEM);
    cudaFuncSetAttribute(k_gru, cudaFuncAttributeMaxDynamicSharedMemorySize, GRU_SMEM);

    k_zero<<<(NPMAX * Dh + 255) / 256, 256>>>();
    k_prep<<<3200, 256>>>(aW1, aW2, aW3, gWih, gWhh);
    int tot_cs = NLV * Epad + NLV * NP;
    k_count<<<(tot_cs + 255) / 256, 256>>>(egate_lv, ngate_lv, Epad, NP);
    k_scan<<<1, 32>>>();
    k_scatter<<<(tot_cs + 255) / 256, 256>>>(egate_lv, ngate_lv, Epad, NP);
    k_inputs<<<(N + 63) / 64, 256, SM_IN>>>(x, Ws, Wt, sb, tb, hb, N);

    int mlp_grid = (Epad + TILE_E - 1) / TILE_E + 5;
    int gru_grid = (NP + TILE_G - 1) / TILE_G + 5;
    for (int l = 0; l < NLV; l++) {
        k_mlp<<<mlp_grid, 256, MLP_SMEM>>>(ab1, ab2, ab3, src_lv, dpos_lv, sb, hb, l, Epad);
        k_gru<<<gru_grid, 256, GRU_SMEM>>>(gbih, gbhh, node_lv, sb, hb, l, NP);
    }
}

// round 6
// speedup vs baseline: 1.6439x; 1.2908x over previous
#include <cuda_runtime.h>
#include <cuda_bf16.h>
#include <cstdint>

#define Dh 128
#define DINx 64
#define NLV 15
#define EMAX 20480
#define NPMAX 8192
#define TILE_E 64
#define TILE_G 32

__device__ float g_msg[NPMAX * Dh];
__device__ int g_eperm[NLV * EMAX];
__device__ int g_nperm[NLV * NPMAX];
__device__ int g_ecnt[NLV][5], g_ncnt[NLV][5];
__device__ int g_ecur[NLV][5], g_ncur[NLV][5];
__device__ int g_eoff[NLV][5], g_noff[NLV][5];
__device__ int g_etile[NLV][6], g_ntile[NLV][6];

__device__ __nv_bfloat16 g_W1h[5 * 256 * 128], g_W1l[5 * 256 * 128];
__device__ __nv_bfloat16 g_W2h[5 * 128 * 128], g_W2l[5 * 128 * 128];
__device__ __nv_bfloat16 g_W3h[5 * 128 * 128], g_W3l[5 * 128 * 128];
__device__ __nv_bfloat16 g_Wih_h[5 * 128 * 384], g_Wih_l[5 * 128 * 384];
__device__ __nv_bfloat16 g_Whh_h[5 * 128 * 384], g_Whh_l[5 * 128 * 384];

__constant__ int c_TI[6] = {0, 3, 1, 0, 4, 2};

__device__ __forceinline__ float sigmf(float x) { return 1.f / (1.f + __expf(-x)); }
__device__ __forceinline__ float tanhff(float x) { float e = __expf(2.f * x); return 1.f - 2.f / (e + 1.f); }

__device__ __forceinline__ void splitbf(float v, __nv_bfloat16* h, __nv_bfloat16* l) {
    __nv_bfloat16 hh = __float2bfloat16_rn(v);
    *h = hh;
    *l = __float2bfloat16_rn(v - __bfloat162float(hh));
}

__device__ __forceinline__ void ldsm4(uint32_t r[4], const void* p) {
    unsigned int a = (unsigned int)__cvta_generic_to_shared(p);
    asm volatile("ldmatrix.sync.aligned.m8n8.x4.shared.b16 {%0,%1,%2,%3},[%4];"
                 : "=r"(r[0]), "=r"(r[1]), "=r"(r[2]), "=r"(r[3]) : "r"(a));
}
__device__ __forceinline__ void ldsm4t(uint32_t r[4], const void* p) {
    unsigned int a = (unsigned int)__cvta_generic_to_shared(p);
    asm volatile("ldmatrix.sync.aligned.m8n8.x4.trans.shared.b16 {%0,%1,%2,%3},[%4];"
                 : "=r"(r[0]), "=r"(r[1]), "=r"(r[2]), "=r"(r[3]) : "r"(a));
}
__device__ __forceinline__ void mma_bf(float c[4], const uint32_t a[4], uint32_t b0, uint32_t b1) {
    asm volatile(
        "mma.sync.aligned.m16n8k16.row.col.f32.bf16.bf16.f32 "
        "{%0,%1,%2,%3},{%4,%5,%6,%7},{%8,%9},{%0,%1,%2,%3};"
        : "+f"(c[0]), "+f"(c[1]), "+f"(c[2]), "+f"(c[3])
        : "r"(a[0]), "r"(a[1]), "r"(a[2]), "r"(a[3]), "r"(b0), "r"(b1));
}

// ---------------- setup ----------------
__global__ __launch_bounds__(256) void k_zero() {
    int i = blockIdx.x * blockDim.x + threadIdx.x;
    if (i < NPMAX * Dh) g_msg[i] = 0.f;
    if (i < NLV * 5) {
        int l = i / 5, t = i % 5;
        g_ecnt[l][t] = 0; g_ncnt[l][t] = 0; g_ecur[l][t] = 0; g_ncur[l][t] = 0;
    }
}

__global__ __launch_bounds__(256) void k_prep(const float* __restrict__ aW1, const float* __restrict__ aW2,
                                              const float* __restrict__ aW3, const float* __restrict__ gWih,
                                              const float* __restrict__ gWhh) {
    int i = blockIdx.x * 256 + threadIdx.x;
    if (i < 163840) splitbf(aW1[i], &g_W1h[i], &g_W1l[i]);
    else if (i < 245760) { int j = i - 163840; splitbf(aW2[j], &g_W2h[j], &g_W2l[j]); }
    else if (i < 327680) { int j = i - 245760; splitbf(aW3[j], &g_W3h[j], &g_W3l[j]); }
    else if (i < 573440) { int j = i - 327680; splitbf(gWih[j], &g_Wih_h[j], &g_Wih_l[j]); }
    else if (i < 819200) { int j = i - 573440; splitbf(gWhh[j], &g_Whh_h[j], &g_Whh_l[j]); }
}

__global__ __launch_bounds__(256) void k_count(const int* __restrict__ eg, const int* __restrict__ ng, int Epad, int NP) {
    __shared__ int hist[150];
    int tid = threadIdx.x;
    if (tid < 150) hist[tid] = 0;
    __syncthreads();
    int i = blockIdx.x * 256 + tid;
    int ne = NLV * Epad;
    if (i < ne) {
        int g = eg[i];
        if (g > 0) atomicAdd(&hist[(i / Epad) * 5 + g - 1], 1);
    } else {
        int j = i - ne;
        if (j < NLV * NP) {
            int g = ng[j];
            if (g > 0) atomicAdd(&hist[75 + (j / NP) * 5 + g - 1], 1);
        }
    }
    __syncthreads();
    if (tid < 75 && hist[tid]) atomicAdd(&((int*)g_ecnt)[tid], hist[tid]);
    if (tid >= 75 && tid < 150 && hist[tid]) atomicAdd(&((int*)g_ncnt)[tid - 75], hist[tid]);
}

__global__ void k_scan() {
    int l = threadIdx.x;
    if (l >= NLV) return;
    int off = 0, to = 0;
    for (int t = 0; t < 5; t++) {
        g_eoff[l][t] = off; g_etile[l][t] = to;
        off += g_ecnt[l][t]; to += (g_ecnt[l][t] + TILE_E - 1) / TILE_E;
    }
    g_etile[l][5] = to;
    off = 0; to = 0;
    for (int t = 0; t < 5; t++) {
        g_noff[l][t] = off; g_ntile[l][t] = to;
        off += g_ncnt[l][t]; to += (g_ncnt[l][t] + TILE_G - 1) / TILE_G;
    }
    g_ntile[l][5] = to;
}

__global__ __launch_bounds__(256) void k_scatter(const int* __restrict__ eg, const int* __restrict__ ng, int Epad, int NP) {
    __shared__ int hist[150], basev[150], lcur[150];
    int tid = threadIdx.x;
    if (tid < 150) { hist[tid] = 0; lcur[tid] = 0; }
    __syncthreads();
    int i = blockIdx.x * 256 + tid;
    int ne = NLV * Epad;
    int bin = -1;
    if (i < ne) {
        int g = eg[i];
        if (g > 0) bin = (i / Epad) * 5 + g - 1;
    } else {
        int j = i - ne;
        if (j < NLV * NP) {
            int g = ng[j];
            if (g > 0) bin = 75 + (j / NP) * 5 + g - 1;
        }
    }
    if (bin >= 0) atomicAdd(&hist[bin], 1);
    __syncthreads();
    if (tid < 75 && hist[tid]) basev[tid] = atomicAdd(&((int*)g_ecur)[tid], hist[tid]);
    if (tid >= 75 && tid < 150 && hist[tid]) basev[tid] = atomicAdd(&((int*)g_ncur)[tid - 75], hist[tid]);
    __syncthreads();
    if (bin >= 0) {
        int p = basev[bin] + atomicAdd(&lcur[bin], 1);
        if (bin < 75) {
            int l = bin / 5;
            g_eperm[l * EMAX + ((int*)g_eoff)[bin] + p] = i % Epad;
        } else {
            int l = (bin - 75) / 5;
            g_nperm[l * NPMAX + ((int*)g_noff)[bin - 75] + p] = (i - ne) % NP;
        }
    }
}

// ---------------- input projections ----------------
__global__ __launch_bounds__(256)
void k_inputs(const float* __restrict__ x, const float* __restrict__ Ws, const float* __restrict__ Wt,
              float* __restrict__ sb, float* __restrict__ tb, float* __restrict__ hb, int N) {
    extern __shared__ float sm[];
    float* smx = sm;
    float* sws = sm + 4096;
    float* swt = sws + 8192;
    int tid = threadIdx.x, row0 = blockIdx.x * 64;
    for (int i = tid; i < 8192; i += 256) { sws[i] = Ws[i]; swt[i] = Wt[i]; }
    for (int i = tid; i < 4096; i += 256) {
        int r = i >> 6, gr = row0 + r;
        smx[i] = (gr < N) ? x[gr * DINx + (i & 63)] : 0.f;
    }
    __syncthreads();
    int tx = tid & 31, ty = tid >> 5;
    float as[8][4] = {}, at[8][4] = {};
    #pragma unroll 4
    for (int k = 0; k < 64; k++) {
        float4 bs = *(float4*)&sws[k * 128 + tx * 4];
        float4 bt = *(float4*)&swt[k * 128 + tx * 4];
        #pragma unroll
        for (int r = 0; r < 8; r++) {
            float a = smx[(ty * 8 + r) * 64 + k];
            as[r][0] += a * bs.x; as[r][1] += a * bs.y; as[r][2] += a * bs.z; as[r][3] += a * bs.w;
            at[r][0] += a * bt.x; at[r][1] += a * bt.y; at[r][2] += a * bt.z; at[r][3] += a * bt.w;
        }
    }
    #pragma unroll
    for (int r = 0; r < 8; r++) {
        int gr = row0 + ty * 8 + r;
        if (gr < N) {
            *(float4*)&sb[gr * Dh + tx * 4] = make_float4(as[r][0], as[r][1], as[r][2], as[r][3]);
            *(float4*)&tb[gr * Dh + tx * 4] = make_float4(at[r][0], at[r][1], at[r][2], at[r][3]);
            *(float4*)&hb[gr * Dh + tx * 4] = make_float4(0.f, 0.f, 0.f, 0.f);
        }
    }
}

// ---------------- MLP: 64-edge tile; smem 104KB -> 2 CTAs/SM ----------------
// R0[34816]: layer1 Ah (stride 264) -> H1h/H1l (stride 136)
// R1[34816]: layer1 Al (stride 264) -> H2h/H2l (stride 136)
// W [34816]: Wh/Wl (stride 136)
#define MLP_SMEM 104448
__global__ __launch_bounds__(256, 2)
void k_mlp(const float* __restrict__ B1, const float* __restrict__ B2, const float* __restrict__ B3,
           const int* __restrict__ src_lv, const int* __restrict__ dpos_lv,
           const float* __restrict__ sb, const float* __restrict__ hb, int level, int Epad) {
    extern __shared__ char smc[];
    __nv_bfloat16* R0 = (__nv_bfloat16*)smc;
    __nv_bfloat16* R1 = (__nv_bfloat16*)(smc + 34816);
    __nv_bfloat16* Wh = (__nv_bfloat16*)(smc + 69632);
    __nv_bfloat16* Wl = (__nv_bfloat16*)(smc + 87040);
    __shared__ int s_src[TILE_E], s_dp[TILE_E], s_meta[3];

    int tid = threadIdx.x;
    if (tid == 0) {
        int b = blockIdx.x, tot = g_etile[level][5], tc = -1, base = 0, ne = 0;
        if (b < tot) {
            int t2 = 0;
            while (b >= g_etile[level][t2 + 1]) t2++;
            base = g_eoff[level][t2] + (b - g_etile[level][t2]) * TILE_E;
            ne = min(TILE_E, g_eoff[level][t2] + g_ecnt[level][t2] - base);
            tc = t2;
        }
        s_meta[0] = tc; s_meta[1] = base; s_meta[2] = ne;
    }
    __syncthreads();
    int tc = s_meta[0];
    if (tc < 0) return;
    int base = s_meta[1], ne = s_meta[2], ti = c_TI[tc + 1];
    for (int i = tid; i < ne; i += 256) {
        int e = g_eperm[level * EMAX + base + i];
        s_src[i] = src_lv[level * Epad + e];
        s_dp[i] = dpos_lv[level * Epad + e];
    }
    __syncthreads();
    for (int i = tid; i < 64 * 256; i += 256) {
        int r = i >> 8, c = i & 255;
        float v = 0.f;
        if (r < ne) {
            int s = s_src[r];
            v = (c < 128) ? sb[s * Dh + c] : hb[s * Dh + (c - 128)];
        }
        splitbf(v, &R0[r * 264 + c], &R1[r * 264 + c]);
    }

    int lane = tid & 31, warp = tid >> 5, wr = warp >> 1, wc = warp & 1;
    float acc[8][4];

    auto run_gemm = [&](const __nv_bfloat16* sAh, const __nv_bfloat16* sAl, int lda, int K,
                        const __nv_bfloat16* gwh, const __nv_bfloat16* gwl) {
        #pragma unroll
        for (int t = 0; t < 8; t++) { acc[t][0] = acc[t][1] = acc[t][2] = acc[t][3] = 0.f; }
        for (int kc = 0; kc < K; kc += 64) {
            __syncthreads();
            for (int i = tid; i < 4096; i += 256) {
                int r = i >> 6, c2 = (i & 63) << 1;
                *(uint32_t*)&Wh[r * 136 + c2] = *(const uint32_t*)&gwh[(kc + r) * 128 + c2];
                *(uint32_t*)&Wl[r * 136 + c2] = *(const uint32_t*)&gwl[(kc + r) * 128 + c2];
            }
            __syncthreads();
            #pragma unroll
            for (int ks = 0; ks < 4; ks++) {
                int k0 = ks << 4;
                uint32_t ah[4], al[4];
                const __nv_bfloat16* ap = sAh + (wr * 16 + (lane & 15)) * lda + kc + k0 + ((lane >> 4) << 3);
                ldsm4(ah, ap);
                ldsm4(al, sAl + (ap - sAh));
                #pragma unroll
                for (int g = 0; g < 4; g++) {
                    int c0 = wc * 64 + (g << 4);
                    uint32_t bh[4], bl[4];
                    const __nv_bfloat16* bp = Wh + (k0 + (lane & 15)) * 136 + c0 + ((lane >> 4) << 3);
                    ldsm4t(bh, bp);
                    ldsm4t(bl, Wl + (bp - Wh));
                    mma_bf(acc[2 * g], ah, bh[0], bh[1]);
                    mma_bf(acc[2 * g], ah, bl[0], bl[1]);
                    mma_bf(acc[2 * g], al, bh[0], bh[1]);
                    mma_bf(acc[2 * g + 1], ah, bh[2], bh[3]);
                    mma_bf(acc[2 * g + 1], ah, bl[2], bl[3]);
                    mma_bf(acc[2 * g + 1], al, bh[2], bh[3]);
                }
            }
        }
        __syncthreads();
    };

    int r1 = wr * 16 + (lane >> 2), r2 = r1 + 8;

    auto store_relu = [&](__nv_bfloat16* Dhp, __nv_bfloat16* Dlp, const float* bias) {
        #pragma unroll
        for (int t = 0; t < 8; t++) {
            int col = wc * 64 + t * 8 + ((lane & 3) << 1);
            float b0 = bias[col], b1 = bias[col + 1];
            splitbf(fmaxf(acc[t][0] + b0, 0.f), &Dhp[r1 * 136 + col], &Dlp[r1 * 136 + col]);
            splitbf(fmaxf(acc[t][1] + b1, 0.f), &Dhp[r1 * 136 + col + 1], &Dlp[r1 * 136 + col + 1]);
            splitbf(fmaxf(acc[t][2] + b0, 0.f), &Dhp[r2 * 136 + col], &Dlp[r2 * 136 + col]);
            splitbf(fmaxf(acc[t][3] + b1, 0.f), &Dhp[r2 * 136 + col + 1], &Dlp[r2 * 136 + col + 1]);
        }
    };

    // layer 1: A = feats (R0 hi, R1 lo, stride 264)
    run_gemm(R0, R1, 264, 256, g_W1h + ti * 32768, g_W1l + ti * 32768);
    store_relu(R0, R0 + 8704, B1 + ti * Dh);       // H1 -> R0 (hi at 0, lo at +17408B)
    __syncthreads();
    // layer 2: A = H1
    run_gemm(R0, R0 + 8704, 136, 128, g_W2h + ti * 16384, g_W2l + ti * 16384);
    store_relu(R1, R1 + 8704, B2 + ti * Dh);       // H2 -> R1
    __syncthreads();
    // layer 3: A = H2 -> scatter-add
    run_gemm(R1, R1 + 8704, 136, 128, g_W3h + ti * 16384, g_W3l + ti * 16384);
    {
        const float* bias = B3 + ti * Dh;
        #pragma unroll
        for (int t = 0; t < 8; t++) {
            int col = wc * 64 + t * 8 + ((lane & 3) << 1);
            float b0 = bias[col], b1 = bias[col + 1];
            if (r1 < ne) {
                float* mp = &g_msg[s_dp[r1] * Dh + col];
                atomicAdd(mp, acc[t][0] + b0);
                atomicAdd(mp + 1, acc[t][1] + b1);
            }
            if (r2 < ne) {
                float* mp = &g_msg[s_dp[r2] * Dh + col];
                atomicAdd(mp, acc[t][2] + b0);
                atomicAdd(mp + 1, acc[t][3] + b1);
            }
        }
    }
}

// ---------------- GRU: 32-node tile; gates in registers; smem 85KB -> 2 CTAs/SM ----------------
// Warp wc owns col strip j0=wc*32 in r/z/n regions: groups g: col = (g>>1)*128 + j0 + (g&1)*16
#define GRU_SMEM 84992
__global__ __launch_bounds__(256, 2)
void k_gru(const float* __restrict__ gbih, const float* __restrict__ gbhh,
           const int* __restrict__ node_lv, float* __restrict__ sb, float* __restrict__ hb,
           int level, int NP) {
    extern __shared__ char smc[];
    __nv_bfloat16* Xh = (__nv_bfloat16*)smc;
    __nv_bfloat16* Xl = (__nv_bfloat16*)(smc + 8704);
    __nv_bfloat16* Hh = (__nv_bfloat16*)(smc + 17408);
    __nv_bfloat16* Hl = (__nv_bfloat16*)(smc + 26112);
    __nv_bfloat16* Wh = (__nv_bfloat16*)(smc + 34816);
    __nv_bfloat16* Wl = (__nv_bfloat16*)(smc + 59904);
    __shared__ int s_pos[TILE_G], s_node[TILE_G], s_meta[3];

    int tid = threadIdx.x;
    if (tid == 0) {
        int b = blockIdx.x, tot = g_ntile[level][5], tc = -1, base = 0, nn = 0;
        if (b < tot) {
            int t2 = 0;
            while (b >= g_ntile[level][t2 + 1]) t2++;
            base = g_noff[level][t2] + (b - g_ntile[level][t2]) * TILE_G;
            nn = min(TILE_G, g_noff[level][t2] + g_ncnt[level][t2] - base);
            tc = t2;
        }
        s_meta[0] = tc; s_meta[1] = base; s_meta[2] = nn;
    }
    __syncthreads();
    int tc = s_meta[0];
    if (tc < 0) return;
    int base = s_meta[1], nn = s_meta[2], ti = c_TI[tc + 1];
    for (int i = tid; i < nn; i += 256) {
        int p = g_nperm[level * NPMAX + base + i];
        s_pos[i] = p;
        s_node[i] = node_lv[level * NP + p];
    }
    __syncthreads();
    for (int i = tid; i < 32 * 128; i += 256) {
        int r = i >> 7, c = i & 127;
        float xv = 0.f, hv = 0.f;
        if (r < nn) {
            int p = s_pos[r];
            xv = g_msg[p * Dh + c];
            g_msg[p * Dh + c] = 0.f;
            hv = hb[s_node[r] * Dh + c];
        }
        splitbf(xv, &Xh[r * 136 + c], &Xl[r * 136 + c]);
        splitbf(hv, &Hh[r * 136 + c], &Hl[r * 136 + c]);
    }

    int lane = tid & 31, warp = tid >> 5, wr = warp >> 2, wc = warp & 3;
    int j0 = wc * 32;
    float gi[12][4], gh[12][4];

    auto run_gemm = [&](float (*acc)[4], const __nv_bfloat16* sAh, const __nv_bfloat16* sAl,
                        const __nv_bfloat16* gwh, const __nv_bfloat16* gwl) {
        #pragma unroll
        for (int t = 0; t < 12; t++) { acc[t][0] = acc[t][1] = acc[t][2] = acc[t][3] = 0.f; }
        for (int kc = 0; kc < 128; kc += 32) {
            __syncthreads();
            for (int i = tid; i < 6144; i += 256) {
                int r = i / 192, c2 = (i % 192) * 2;
                *(uint32_t*)&Wh[r * 392 + c2] = *(const uint32_t*)&gwh[(kc + r) * 384 + c2];
                *(uint32_t*)&Wl[r * 392 + c2] = *(const uint32_t*)&gwl[(kc + r) * 384 + c2];
            }
            __syncthreads();
            #pragma unroll
            for (int ks = 0; ks < 2; ks++) {
                int k0 = ks << 4;
                uint32_t ah[4], al[4];
                const __nv_bfloat16* ap = sAh + (wr * 16 + (lane & 15)) * 136 + kc + k0 + ((lane >> 4) << 3);
                ldsm4(ah, ap);
                ldsm4(al, sAl + (ap - sAh));
                #pragma unroll
                for (int g = 0; g < 6; g++) {
                    int c0 = (g >> 1) * 128 + j0 + ((g & 1) << 4);
                    uint32_t bh[4], bl[4];
                    const __nv_bfloat16* bp = Wh + (k0 + (lane & 15)) * 392 + c0 + ((lane >> 4) << 3);
                    ldsm4t(bh, bp);
                    ldsm4t(bl, Wl + (bp - Wh));
                    mma_bf(acc[2 * g], ah, bh[0], bh[1]);
                    mma_bf(acc[2 * g], ah, bl[0], bl[1]);
                    mma_bf(acc[2 * g], al, bh[0], bh[1]);
                    mma_bf(acc[2 * g + 1], ah, bh[2], bh[3]);
                    mma_bf(acc[2 * g + 1], ah, bl[2], bl[3]);
                    mma_bf(acc[2 * g + 1], al, bh[2], bh[3]);
                }
            }
        }
        __syncthreads();
    };

    int r1 = wr * 16 + (lane >> 2), r2 = r1 + 8;
    // col of acc[t][v]: (t>>2)*128 + j0 + (t&3)*8 + (lane&3)*2 + (v&1); row = v<2 ? r1 : r2

    run_gemm(gi, Xh, Xl, g_Wih_h + ti * 49152, g_Wih_l + ti * 49152);
    {
        const float* bp = gbih + ti * 384;
        #pragma unroll
        for (int t = 0; t < 12; t++) {
            int col = (t >> 2) * 128 + j0 + (t & 3) * 8 + ((lane & 3) << 1);
            float b0 = bp[col], b1 = bp[col + 1];
            gi[t][0] += b0; gi[t][1] += b1; gi[t][2] += b0; gi[t][3] += b1;
        }
    }

    int npass = (tc == 2) ? 2 : 1;   // AND also refreshes s
    for (int pass = 0; pass < npass; pass++) {
        if (pass == 1) {
            for (int i = tid; i < 32 * 128; i += 256) {
                int r = i >> 7, c = i & 127;
                float hv = (r < nn) ? sb[s_node[r] * Dh + c] : 0.f;
                splitbf(hv, &Hh[r * 136 + c], &Hl[r * 136 + c]);
            }
            __syncthreads();
        }
        run_gemm(gh, Hh, Hl, g_Whh_h + ti * 49152, g_Whh_l + ti * 49152);
        {
            const float* bp = gbhh + ti * 384;
            #pragma unroll
            for (int t = 0; t < 12; t++) {
                int col = (t >> 2) * 128 + j0 + (t & 3) * 8 + ((lane & 3) << 1);
                float b0 = bp[col], b1 = bp[col + 1];
                gh[t][0] += b0; gh[t][1] += b1; gh[t][2] += b0; gh[t][3] += b1;
            }
        }
        float* target = pass ? sb : hb;
        #pragma unroll
        for (int m = 0; m < 4; m++) {
            #pragma unroll
            for (int v = 0; v < 4; v++) {
                int row = (v < 2) ? r1 : r2;
                if (row < nn) {
                    int col = j0 + m * 8 + ((lane & 3) << 1) + (v & 1);
                    float rv = sigmf(gi[m][v] + gh[m][v]);
                    float zv = sigmf(gi[4 + m][v] + gh[4 + m][v]);
                    float nv = tanhff(gi[8 + m][v] + rv * gh[8 + m][v]);
                    float h = __bfloat162float(Hh[row * 136 + col]) + __bfloat162float(Hl[row * 136 + col]);
                    target[s_node[row] * Dh + col] = (1.f - zv) * nv + zv * h;
                }
            }
        }
        __syncthreads();
    }
}

extern "C" void kernel_launch(void* const* d_in, const int* in_sizes, int n_in,
                              void* d_out, int out_size) {
    const float* x = (const float*)d_in[0];
    const float* Ws = (const float*)d_in[1];
    const float* Wt = (const float*)d_in[2];
    const float* aW1 = (const float*)d_in[3];
    const float* ab1 = (const float*)d_in[4];
    const float* aW2 = (const float*)d_in[5];
    const float* ab2 = (const float*)d_in[6];
    const float* aW3 = (const float*)d_in[7];
    const float* ab3 = (const float*)d_in[8];
    const float* gWih = (const float*)d_in[9];
    const float* gWhh = (const float*)d_in[10];
    const float* gbih = (const float*)d_in[11];
    const float* gbhh = (const float*)d_in[12];
    const int* src_lv = (const int*)d_in[13];
    const int* dpos_lv = (const int*)d_in[14];
    const int* egate_lv = (const int*)d_in[15];
    const int* node_lv = (const int*)d_in[16];
    const int* ngate_lv = (const int*)d_in[17];

    int N = in_sizes[0] / DINx;
    int Epad = in_sizes[13] / NLV;
    int NP = in_sizes[16] / NLV;

    float* sb = (float*)d_out;
    float* tb = sb + (size_t)N * Dh;
    float* hb = tb + (size_t)N * Dh;

    const int SM_IN = (4096 + 2 * 8192) * 4;
    cudaFuncSetAttribute(k_inputs, cudaFuncAttributeMaxDynamicSharedMemorySize, SM_IN);
    cudaFuncSetAttribute(k_mlp, cudaFuncAttributeMaxDynamicSharedMemorySize, MLP_SMEM);
    cudaFuncSetAttribute(k_gru, cudaFuncAttributeMaxDynamicSharedMemorySize, GRU_SMEM);

    k_zero<<<(NPMAX * Dh + 255) / 256, 256>>>();
    k_prep<<<3200, 256>>>(aW1, aW2, aW3, gWih, gWhh);
    int tot_cs = NLV * Epad + NLV * NP;
    k_count<<<(tot_cs + 255) / 256, 256>>>(egate_lv, ngate_lv, Epad, NP);
    k_scan<<<1, 32>>>();
    k_scatter<<<(tot_cs + 255) / 256, 256>>>(egate_lv, ngate_lv, Epad, NP);
    k_inputs<<<(N + 63) / 64, 256, SM_IN>>>(x, Ws, Wt, sb, tb, hb, N);

    int mlp_grid = (Epad + TILE_E - 1) / TILE_E + 5;
    int gru_grid = (NP + TILE_G - 1) / TILE_G + 5;
    for (int l = 0; l < NLV; l++) {
        k_mlp<<<mlp_grid, 256, MLP_SMEM>>>(ab1, ab2, ab3, src_lv, dpos_lv, sb, hb, l, Epad);
        k_gru<<<gru_grid, 256, GRU_SMEM>>>(gbih, gbhh, node_lv, sb, hb, l, NP);
    }
}

// round 8
// speedup vs baseline: 1.8057x; 1.0984x over previous
#include <cuda_runtime.h>
#include <cuda_bf16.h>
#include <cstdint>

#define Dh 128
#define DINx 64
#define NLV 15
#define EMAX 20480
#define NPMAX 8192
#define TILE_E 64
#define TILE_G 32

__device__ float g_msg[NPMAX * Dh];
__device__ int g_eperm[NLV * EMAX];
__device__ int g_nperm[NLV * NPMAX];
__device__ int g_ecnt[NLV][5], g_ncnt[NLV][5];
__device__ int g_ecur[NLV][5], g_ncur[NLV][5];
__device__ int g_eoff[NLV][5], g_noff[NLV][5];
__device__ int g_etile[NLV][6], g_ntile[NLV][6];

__device__ __nv_bfloat16 g_W1h[5 * 256 * 128], g_W1l[5 * 256 * 128];
__device__ __nv_bfloat16 g_W2h[5 * 128 * 128], g_W2l[5 * 128 * 128];
__device__ __nv_bfloat16 g_W3h[5 * 128 * 128], g_W3l[5 * 128 * 128];
__device__ __nv_bfloat16 g_Wih_h[5 * 128 * 384], g_Wih_l[5 * 128 * 384];
__device__ __nv_bfloat16 g_Whh_h[5 * 128 * 384], g_Whh_l[5 * 128 * 384];

__constant__ int c_TI[6] = {0, 3, 1, 0, 4, 2};

__device__ __forceinline__ float sigmf(float x) { return 1.f / (1.f + __expf(-x)); }
__device__ __forceinline__ float tanhff(float x) { float e = __expf(2.f * x); return 1.f - 2.f / (e + 1.f); }

__device__ __forceinline__ void splitbf(float v, __nv_bfloat16* h, __nv_bfloat16* l) {
    __nv_bfloat16 hh = __float2bfloat16_rn(v);
    *h = hh;
    *l = __float2bfloat16_rn(v - __bfloat162float(hh));
}

__device__ __forceinline__ void ldsm4(uint32_t r[4], const void* p) {
    unsigned int a = (unsigned int)__cvta_generic_to_shared(p);
    asm volatile("ldmatrix.sync.aligned.m8n8.x4.shared.b16 {%0,%1,%2,%3},[%4];"
                 : "=r"(r[0]), "=r"(r[1]), "=r"(r[2]), "=r"(r[3]) : "r"(a));
}
__device__ __forceinline__ void ldsm4t(uint32_t r[4], const void* p) {
    unsigned int a = (unsigned int)__cvta_generic_to_shared(p);
    asm volatile("ldmatrix.sync.aligned.m8n8.x4.trans.shared.b16 {%0,%1,%2,%3},[%4];"
                 : "=r"(r[0]), "=r"(r[1]), "=r"(r[2]), "=r"(r[3]) : "r"(a));
}
__device__ __forceinline__ void mma_bf(float c[4], const uint32_t a[4], uint32_t b0, uint32_t b1) {
    asm volatile(
        "mma.sync.aligned.m16n8k16.row.col.f32.bf16.bf16.f32 "
        "{%0,%1,%2,%3},{%4,%5,%6,%7},{%8,%9},{%0,%1,%2,%3};"
        : "+f"(c[0]), "+f"(c[1]), "+f"(c[2]), "+f"(c[3])
        : "r"(a[0]), "r"(a[1]), "r"(a[2]), "r"(a[3]), "r"(b0), "r"(b1));
}
__device__ __forceinline__ void cpa16(void* smem, const void* gmem) {
    unsigned int a = (unsigned int)__cvta_generic_to_shared(smem);
    asm volatile("cp.async.ca.shared.global [%0],[%1],16;" :: "r"(a), "l"(gmem));
}
__device__ __forceinline__ void cp_commit() { asm volatile("cp.async.commit_group;"); }
template<int N> __device__ __forceinline__ void cp_wait() { asm volatile("cp.async.wait_group %0;" :: "n"(N)); }

// ---------------- setup: zero + weight split fused ----------------
__global__ __launch_bounds__(256) void k_prep(const float* __restrict__ aW1, const float* __restrict__ aW2,
                                              const float* __restrict__ aW3, const float* __restrict__ gWih,
                                              const float* __restrict__ gWhh) {
    int i = blockIdx.x * 256 + threadIdx.x;
    if (i < NPMAX * Dh) g_msg[i] = 0.f;
    if (i < NLV * 5) {
        ((int*)g_ecnt)[i] = 0; ((int*)g_ncnt)[i] = 0;
        ((int*)g_ecur)[i] = 0; ((int*)g_ncur)[i] = 0;
    }
    if (i < 163840) splitbf(aW1[i], &g_W1h[i], &g_W1l[i]);
    else if (i < 245760) { int j = i - 163840; splitbf(aW2[j], &g_W2h[j], &g_W2l[j]); }
    else if (i < 327680) { int j = i - 245760; splitbf(aW3[j], &g_W3h[j], &g_W3l[j]); }
    else if (i < 573440) { int j = i - 327680; splitbf(gWih[j], &g_Wih_h[j], &g_Wih_l[j]); }
    else if (i < 819200) { int j = i - 573440; splitbf(gWhh[j], &g_Whh_h[j], &g_Whh_l[j]); }
}

__global__ __launch_bounds__(256) void k_count(const int* __restrict__ eg, const int* __restrict__ ng, int Epad, int NP) {
    __shared__ int hist[150];
    int tid = threadIdx.x;
    if (tid < 150) hist[tid] = 0;
    __syncthreads();
    int i = blockIdx.x * 256 + tid;
    int ne = NLV * Epad;
    if (i < ne) {
        int g = eg[i];
        if (g > 0) atomicAdd(&hist[(i / Epad) * 5 + g - 1], 1);
    } else {
        int j = i - ne;
        if (j < NLV * NP) {
            int g = ng[j];
            if (g > 0) atomicAdd(&hist[75 + (j / NP) * 5 + g - 1], 1);
        }
    }
    __syncthreads();
    if (tid < 75 && hist[tid]) atomicAdd(&((int*)g_ecnt)[tid], hist[tid]);
    if (tid >= 75 && tid < 150 && hist[tid]) atomicAdd(&((int*)g_ncnt)[tid - 75], hist[tid]);
}

__global__ void k_scan() {
    int l = threadIdx.x;
    if (l >= NLV) return;
    int off = 0, to = 0;
    for (int t = 0; t < 5; t++) {
        g_eoff[l][t] = off; g_etile[l][t] = to;
        off += g_ecnt[l][t]; to += (g_ecnt[l][t] + TILE_E - 1) / TILE_E;
    }
    g_etile[l][5] = to;
    off = 0; to = 0;
    for (int t = 0; t < 5; t++) {
        g_noff[l][t] = off; g_ntile[l][t] = to;
        off += g_ncnt[l][t]; to += (g_ncnt[l][t] + TILE_G - 1) / TILE_G;
    }
    g_ntile[l][5] = to;
}

__global__ __launch_bounds__(256) void k_scatter(const int* __restrict__ eg, const int* __restrict__ ng, int Epad, int NP) {
    __shared__ int hist[150], basev[150], lcur[150];
    int tid = threadIdx.x;
    if (tid < 150) { hist[tid] = 0; lcur[tid] = 0; }
    __syncthreads();
    int i = blockIdx.x * 256 + tid;
    int ne = NLV * Epad;
    int bin = -1;
    if (i < ne) {
        int g = eg[i];
        if (g > 0) bin = (i / Epad) * 5 + g - 1;
    } else {
        int j = i - ne;
        if (j < NLV * NP) {
            int g = ng[j];
            if (g > 0) bin = 75 + (j / NP) * 5 + g - 1;
        }
    }
    if (bin >= 0) atomicAdd(&hist[bin], 1);
    __syncthreads();
    if (tid < 75 && hist[tid]) basev[tid] = atomicAdd(&((int*)g_ecur)[tid], hist[tid]);
    if (tid >= 75 && tid < 150 && hist[tid]) basev[tid] = atomicAdd(&((int*)g_ncur)[tid - 75], hist[tid]);
    __syncthreads();
    if (bin >= 0) {
        int p = basev[bin] + atomicAdd(&lcur[bin], 1);
        if (bin < 75) {
            int l = bin / 5;
            g_eperm[l * EMAX + ((int*)g_eoff)[bin] + p] = i % Epad;
        } else {
            int l = (bin - 75) / 5;
            g_nperm[l * NPMAX + ((int*)g_noff)[bin - 75] + p] = (i - ne) % NP;
        }
    }
}

// ---------------- input projections ----------------
__global__ __launch_bounds__(256)
void k_inputs(const float* __restrict__ x, const float* __restrict__ Ws, const float* __restrict__ Wt,
              float* __restrict__ sb, float* __restrict__ tb, float* __restrict__ hb, int N) {
    extern __shared__ float sm[];
    float* smx = sm;
    float* sws = sm + 4096;
    float* swt = sws + 8192;
    int tid = threadIdx.x, row0 = blockIdx.x * 64;
    for (int i = tid; i < 8192; i += 256) { sws[i] = Ws[i]; swt[i] = Wt[i]; }
    for (int i = tid; i < 4096; i += 256) {
        int r = i >> 6, gr = row0 + r;
        smx[i] = (gr < N) ? x[gr * DINx + (i & 63)] : 0.f;
    }
    __syncthreads();
    int tx = tid & 31, ty = tid >> 5;
    float as[8][4] = {}, at[8][4] = {};
    #pragma unroll 4
    for (int k = 0; k < 64; k++) {
        float4 bs = *(float4*)&sws[k * 128 + tx * 4];
        float4 bt = *(float4*)&swt[k * 128 + tx * 4];
        #pragma unroll
        for (int r = 0; r < 8; r++) {
            float a = smx[(ty * 8 + r) * 64 + k];
            as[r][0] += a * bs.x; as[r][1] += a * bs.y; as[r][2] += a * bs.z; as[r][3] += a * bs.w;
            at[r][0] += a * bt.x; at[r][1] += a * bt.y; at[r][2] += a * bt.z; at[r][3] += a * bt.w;
        }
    }
    #pragma unroll
    for (int r = 0; r < 8; r++) {
        int gr = row0 + ty * 8 + r;
        if (gr < N) {
            *(float4*)&sb[gr * Dh + tx * 4] = make_float4(as[r][0], as[r][1], as[r][2], as[r][3]);
            *(float4*)&tb[gr * Dh + tx * 4] = make_float4(at[r][0], at[r][1], at[r][2], at[r][3]);
            *(float4*)&hb[gr * Dh + tx * 4] = make_float4(0.f, 0.f, 0.f, 0.f);
        }
    }
}

// ---------------- MLP: 64-edge tile; double-buffered cp.async weights; 2 CTAs/SM ----------------
// R0[34816B], R1[34816B]: acts; W[34816B] = 2 bufs x (hi 32x136 | lo 32x136)
#define MLP_SMEM 104448
__global__ __launch_bounds__(256, 2)
void k_mlp(const float* __restrict__ B1, const float* __restrict__ B2, const float* __restrict__ B3,
           const int* __restrict__ src_lv, const int* __restrict__ dpos_lv,
           const float* __restrict__ sb, const float* __restrict__ hb, int level, int Epad) {
    extern __shared__ char smc[];
    __nv_bfloat16* R0 = (__nv_bfloat16*)smc;
    __nv_bfloat16* R1 = (__nv_bfloat16*)(smc + 34816);
    __nv_bfloat16* Wbase = (__nv_bfloat16*)(smc + 69632);
    __shared__ int s_src[TILE_E], s_dp[TILE_E], s_meta[3];

    int tid = threadIdx.x;
    if (tid == 0) {
        int b = blockIdx.x, tot = g_etile[level][5], tc = -1, base = 0, ne = 0;
        if (b < tot) {
            int t2 = 0;
            while (b >= g_etile[level][t2 + 1]) t2++;
            base = g_eoff[level][t2] + (b - g_etile[level][t2]) * TILE_E;
            ne = min(TILE_E, g_eoff[level][t2] + g_ecnt[level][t2] - base);
            tc = t2;
        }
        s_meta[0] = tc; s_meta[1] = base; s_meta[2] = ne;
    }
    __syncthreads();
    int tc = s_meta[0];
    if (tc < 0) return;
    int base = s_meta[1], ne = s_meta[2], ti = c_TI[tc + 1];
    for (int i = tid; i < ne; i += 256) {
        int e = g_eperm[level * EMAX + base + i];
        s_src[i] = src_lv[level * Epad + e];
        s_dp[i] = dpos_lv[level * Epad + e];
    }
    __syncthreads();
    for (int i = tid; i < 64 * 256; i += 256) {
        int r = i >> 8, c = i & 255;
        float v = 0.f;
        if (r < ne) {
            int s = s_src[r];
            v = (c < 128) ? sb[s * Dh + c] : hb[s * Dh + (c - 128)];
        }
        splitbf(v, &R0[r * 264 + c], &R1[r * 264 + c]);
    }

    int lane = tid & 31, warp = tid >> 5, wr = warp >> 1, wc = warp & 1;
    float acc[8][4];

    // prefetch one 32-k weight chunk (hi+lo) into buffer buf
    auto prefW = [&](const __nv_bfloat16* gwh, const __nv_bfloat16* gwl, int kc, int buf) {
        __nv_bfloat16* Wb = Wbase + buf * 8704;
        #pragma unroll
        for (int j = 0; j < 2; j++) {
            int i2 = tid * 2 + j;
            int r = i2 >> 4, c8 = (i2 & 15) << 3;
            cpa16(Wb + r * 136 + c8, gwh + (kc + r) * 128 + c8);
            cpa16(Wb + 4352 + r * 136 + c8, gwl + (kc + r) * 128 + c8);
        }
        cp_commit();
    };

    auto run_gemm = [&](const __nv_bfloat16* sAh, const __nv_bfloat16* sAl, int lda, int K,
                        const __nv_bfloat16* gwh, const __nv_bfloat16* gwl) {
        #pragma unroll
        for (int t = 0; t < 8; t++) { acc[t][0] = acc[t][1] = acc[t][2] = acc[t][3] = 0.f; }
        int nch = K >> 5;
        prefW(gwh, gwl, 0, 0);
        for (int c = 0; c < nch; c++) {
            if (c + 1 < nch) { prefW(gwh, gwl, (c + 1) << 5, (c + 1) & 1); cp_wait<1>(); }
            else cp_wait<0>();
            __syncthreads();
            const __nv_bfloat16* Wb = Wbase + (c & 1) * 8704;
            int kc = c << 5;
            #pragma unroll
            for (int ks = 0; ks < 2; ks++) {
                int k0 = ks << 4;
                uint32_t ah[4], al[4];
                const __nv_bfloat16* ap = sAh + (wr * 16 + (lane & 15)) * lda + kc + k0 + ((lane >> 4) << 3);
                ldsm4(ah, ap);
                ldsm4(al, sAl + (ap - sAh));
                #pragma unroll
                for (int g = 0; g < 4; g++) {
                    int c0 = wc * 64 + (g << 4);
                    uint32_t bh[4], bl[4];
                    const __nv_bfloat16* bp = Wb + (k0 + (lane & 15)) * 136 + c0 + ((lane >> 4) << 3);
                    ldsm4t(bh, bp);
                    ldsm4t(bl, bp + 4352);
                    mma_bf(acc[2 * g], ah, bh[0], bh[1]);
                    mma_bf(acc[2 * g], ah, bl[0], bl[1]);
                    mma_bf(acc[2 * g], al, bh[0], bh[1]);
                    mma_bf(acc[2 * g + 1], ah, bh[2], bh[3]);
                    mma_bf(acc[2 * g + 1], ah, bl[2], bl[3]);
                    mma_bf(acc[2 * g + 1], al, bh[2], bh[3]);
                }
            }
            __syncthreads();
        }
    };

    int r1 = wr * 16 + (lane >> 2), r2 = r1 + 8;

    auto store_relu = [&](__nv_bfloat16* Dhp, __nv_bfloat16* Dlp, const float* bias) {
        #pragma unroll
        for (int t = 0; t < 8; t++) {
            int col = wc * 64 + t * 8 + ((lane & 3) << 1);
            float b0 = bias[col], b1 = bias[col + 1];
            splitbf(fmaxf(acc[t][0] + b0, 0.f), &Dhp[r1 * 136 + col], &Dlp[r1 * 136 + col]);
            splitbf(fmaxf(acc[t][1] + b1, 0.f), &Dhp[r1 * 136 + col + 1], &Dlp[r1 * 136 + col + 1]);
            splitbf(fmaxf(acc[t][2] + b0, 0.f), &Dhp[r2 * 136 + col], &Dlp[r2 * 136 + col]);
            splitbf(fmaxf(acc[t][3] + b1, 0.f), &Dhp[r2 * 136 + col + 1], &Dlp[r2 * 136 + col + 1]);
        }
    };

    run_gemm(R0, R1, 264, 256, g_W1h + ti * 32768, g_W1l + ti * 32768);
    store_relu(R0, R0 + 8704, B1 + ti * Dh);
    __syncthreads();
    run_gemm(R0, R0 + 8704, 136, 128, g_W2h + ti * 16384, g_W2l + ti * 16384);
    store_relu(R1, R1 + 8704, B2 + ti * Dh);
    __syncthreads();
    run_gemm(R1, R1 + 8704, 136, 128, g_W3h + ti * 16384, g_W3l + ti * 16384);
    {
        const float* bias = B3 + ti * Dh;
        #pragma unroll
        for (int t = 0; t < 8; t++) {
            int col = wc * 64 + t * 8 + ((lane & 3) << 1);
            float b0 = bias[col], b1 = bias[col + 1];
            if (r1 < ne) {
                float* mp = &g_msg[s_dp[r1] * Dh + col];
                atomicAdd(mp, acc[t][0] + b0);
                atomicAdd(mp + 1, acc[t][1] + b1);
            }
            if (r2 < ne) {
                float* mp = &g_msg[s_dp[r2] * Dh + col];
                atomicAdd(mp, acc[t][2] + b0);
                atomicAdd(mp + 1, acc[t][3] + b1);
            }
        }
    }
}

// ---------------- GRU: 32-node tile; gates in registers; double-buffered weights ----------------
// Xh/Xl/Hh/Hl 4x8704B; W[50176B] = 2 bufs x (hi 16x392 | lo 16x392)
#define GRU_SMEM 84992
__global__ __launch_bounds__(256, 2)
void k_gru(const float* __restrict__ gbih, const float* __restrict__ gbhh,
           const int* __restrict__ node_lv, float* __restrict__ sb, float* __restrict__ hb,
           int level, int NP) {
    extern __shared__ char smc[];
    __nv_bfloat16* Xh = (__nv_bfloat16*)smc;
    __nv_bfloat16* Xl = (__nv_bfloat16*)(smc + 8704);
    __nv_bfloat16* Hh = (__nv_bfloat16*)(smc + 17408);
    __nv_bfloat16* Hl = (__nv_bfloat16*)(smc + 26112);
    __nv_bfloat16* Wbase = (__nv_bfloat16*)(smc + 34816);
    __shared__ int s_pos[TILE_G], s_node[TILE_G], s_meta[3];

    int tid = threadIdx.x;
    if (tid == 0) {
        int b = blockIdx.x, tot = g_ntile[level][5], tc = -1, base = 0, nn = 0;
        if (b < tot) {
            int t2 = 0;
            while (b >= g_ntile[level][t2 + 1]) t2++;
            base = g_noff[level][t2] + (b - g_ntile[level][t2]) * TILE_G;
            nn = min(TILE_G, g_noff[level][t2] + g_ncnt[level][t2] - base);
            tc = t2;
        }
        s_meta[0] = tc; s_meta[1] = base; s_meta[2] = nn;
    }
    __syncthreads();
    int tc = s_meta[0];
    if (tc < 0) return;
    int base = s_meta[1], nn = s_meta[2], ti = c_TI[tc + 1];
    for (int i = tid; i < nn; i += 256) {
        int p = g_nperm[level * NPMAX + base + i];
        s_pos[i] = p;
        s_node[i] = node_lv[level * NP + p];
    }
    __syncthreads();
    for (int i = tid; i < 32 * 128; i += 256) {
        int r = i >> 7, c = i & 127;
        float xv = 0.f, hv = 0.f;
        if (r < nn) {
            int p = s_pos[r];
            xv = g_msg[p * Dh + c];
            g_msg[p * Dh + c] = 0.f;
            hv = hb[s_node[r] * Dh + c];
        }
        splitbf(xv, &Xh[r * 136 + c], &Xl[r * 136 + c]);
        splitbf(hv, &Hh[r * 136 + c], &Hl[r * 136 + c]);
    }

    int lane = tid & 31, warp = tid >> 5, wr = warp >> 2, wc = warp & 3;
    int j0 = wc * 32;
    float gi[12][4], gh[12][4];

    auto prefW = [&](const __nv_bfloat16* gwh, const __nv_bfloat16* gwl, int kc, int buf) {
        __nv_bfloat16* Wb = Wbase + buf * 12544;
        #pragma unroll
        for (int j = 0; j < 3; j++) {
            int i2 = tid * 3 + j;
            int r = i2 / 48, c8 = (i2 % 48) << 3;
            cpa16(Wb + r * 392 + c8, gwh + (kc + r) * 384 + c8);
            cpa16(Wb + 6272 + r * 392 + c8, gwl + (kc + r) * 384 + c8);
        }
        cp_commit();
    };

    auto run_gemm = [&](float (*acc)[4], const __nv_bfloat16* sAh, const __nv_bfloat16* sAl,
                        const __nv_bfloat16* gwh, const __nv_bfloat16* gwl) {
        #pragma unroll
        for (int t = 0; t < 12; t++) { acc[t][0] = acc[t][1] = acc[t][2] = acc[t][3] = 0.f; }
        prefW(gwh, gwl, 0, 0);
        for (int c = 0; c < 8; c++) {
            if (c < 7) { prefW(gwh, gwl, (c + 1) << 4, (c + 1) & 1); cp_wait<1>(); }
            else cp_wait<0>();
            __syncthreads();
            const __nv_bfloat16* Wb = Wbase + (c & 1) * 12544;
            uint32_t ah[4], al[4];
            const __nv_bfloat16* ap = sAh + (wr * 16 + (lane & 15)) * 136 + (c << 4) + ((lane >> 4) << 3);
            ldsm4(ah, ap);
            ldsm4(al, sAl + (ap - sAh));
            #pragma unroll
            for (int g = 0; g < 6; g++) {
                int c0 = (g >> 1) * 128 + j0 + ((g & 1) << 4);
                uint32_t bh[4], bl[4];
                const __nv_bfloat16* bp = Wb + (lane & 15) * 392 + c0 + ((lane >> 4) << 3);
                ldsm4t(bh, bp);
                ldsm4t(bl, bp + 6272);
                mma_bf(acc[2 * g], ah, bh[0], bh[1]);
                mma_bf(acc[2 * g], ah, bl[0], bl[1]);
                mma_bf(acc[2 * g], al, bh[0], bh[1]);
                mma_bf(acc[2 * g + 1], ah, bh[2], bh[3]);
                mma_bf(acc[2 * g + 1], ah, bl[2], bl[3]);
                mma_bf(acc[2 * g + 1], al, bh[2], bh[3]);
            }
            __syncthreads();
        }
    };

    int r1 = wr * 16 + (lane >> 2), r2 = r1 + 8;

    run_gemm(gi, Xh, Xl, g_Wih_h + ti * 49152, g_Wih_l + ti * 49152);
    {
        const float* bp = gbih + ti * 384;
        #pragma unroll
        for (int t = 0; t < 12; t++) {
            int col = (t >> 2) * 128 + j0 + (t & 3) * 8 + ((lane & 3) << 1);
            float b0 = bp[col], b1 = bp[col + 1];
            gi[t][0] += b0; gi[t][1] += b1; gi[t][2] += b0; gi[t][3] += b1;
        }
    }

    int npass = (tc == 2) ? 2 : 1;   // AND also refreshes s
    for (int pass = 0; pass < npass; pass++) {
        if (pass == 1) {
            for (int i = tid; i < 32 * 128; i += 256) {
                int r = i >> 7, c = i & 127;
                float hv = (r < nn) ? sb[s_node[r] * Dh + c] : 0.f;
                splitbf(hv, &Hh[r * 136 + c], &Hl[r * 136 + c]);
            }
            __syncthreads();
        }
        run_gemm(gh, Hh, Hl, g_Whh_h + ti * 49152, g_Whh_l + ti * 49152);
        {
            const float* bp = gbhh + ti * 384;
            #pragma unroll
            for (int t = 0; t < 12; t++) {
                int col = (t >> 2) * 128 + j0 + (t & 3) * 8 + ((lane & 3) << 1);
                float b0 = bp[col], b1 = bp[col + 1];
                gh[t][0] += b0; gh[t][1] += b1; gh[t][2] += b0; gh[t][3] += b1;
            }
        }
        float* target = pass ? sb : hb;
        #pragma unroll
        for (int m = 0; m < 4; m++) {
            #pragma unroll
            for (int v = 0; v < 4; v++) {
                int row = (v < 2) ? r1 : r2;
                if (row < nn) {
                    int col = j0 + m * 8 + ((lane & 3) << 1) + (v & 1);
                    float rv = sigmf(gi[m][v] + gh[m][v]);
                    float zv = sigmf(gi[4 + m][v] + gh[4 + m][v]);
                    float nv = tanhff(gi[8 + m][v] + rv * gh[8 + m][v]);
                    float h = __bfloat162float(Hh[row * 136 + col]) + __bfloat162float(Hl[row * 136 + col]);
                    target[s_node[row] * Dh + col] = (1.f - zv) * nv + zv * h;
                }
            }
        }
        __syncthreads();
    }
}

extern "C" void kernel_launch(void* const* d_in, const int* in_sizes, int n_in,
                              void* d_out, int out_size) {
    const float* x = (const float*)d_in[0];
    const float* Ws = (const float*)d_in[1];
    const float* Wt = (const float*)d_in[2];
    const float* aW1 = (const float*)d_in[3];
    const float* ab1 = (const float*)d_in[4];
    const float* aW2 = (const float*)d_in[5];
    const float* ab2 = (const float*)d_in[6];
    const float* aW3 = (const float*)d_in[7];
    const float* ab3 = (const float*)d_in[8];
    const float* gWih = (const float*)d_in[9];
    const float* gWhh = (const float*)d_in[10];
    const float* gbih = (const float*)d_in[11];
    const float* gbhh = (const float*)d_in[12];
    const int* src_lv = (const int*)d_in[13];
    const int* dpos_lv = (const int*)d_in[14];
    const int* egate_lv = (const int*)d_in[15];
    const int* node_lv = (const int*)d_in[16];
    const int* ngate_lv = (const int*)d_in[17];

    int N = in_sizes[0] / DINx;
    int Epad = in_sizes[13] / NLV;
    int NP = in_sizes[16] / NLV;

    float* sb = (float*)d_out;
    float* tb = sb + (size_t)N * Dh;
    float* hb = tb + (size_t)N * Dh;

    const int SM_IN = (4096 + 2 * 8192) * 4;
    cudaFuncSetAttribute(k_inputs, cudaFuncAttributeMaxDynamicSharedMemorySize, SM_IN);
    cudaFuncSetAttribute(k_mlp, cudaFuncAttributeMaxDynamicSharedMemorySize, MLP_SMEM);
    cudaFuncSetAttribute(k_gru, cudaFuncAttributeMaxDynamicSharedMemorySize, GRU_SMEM);

    k_prep<<<4096, 256>>>(aW1, aW2, aW3, gWih, gWhh);                          // launch 1
    int tot_cs = NLV * Epad + NLV * NP;
    k_count<<<(tot_cs + 255) / 256, 256>>>(egate_lv, ngate_lv, Epad, NP);      // launch 2
    k_scan<<<1, 32>>>();                                                       // launch 3
    k_scatter<<<(tot_cs + 255) / 256, 256>>>(egate_lv, ngate_lv, Epad, NP);    // launch 4
    k_inputs<<<(N + 63) / 64, 256, SM_IN>>>(x, Ws, Wt, sb, tb, hb, N);         // launch 5

    int mlp_grid = (Epad + TILE_E - 1) / TILE_E + 5;
    int gru_grid = (NP + TILE_G - 1) / TILE_G + 5;
    for (int l = 0; l < NLV; l++) {
        k_mlp<<<mlp_grid, 256, MLP_SMEM>>>(ab1, ab2, ab3, src_lv, dpos_lv, sb, hb, l, Epad);  // launch 6 = profiled
        k_gru<<<gru_grid, 256, GRU_SMEM>>>(gbih, gbhh, node_lv, sb, hb, l, NP);
    }
}